// round 13
// baseline (speedup 1.0000x reference)
#include <cuda_runtime.h>
#include <cuda_bf16.h>
#include <math.h>
#include <stdint.h>

#define NVAR 30000
#define NCLS 60000
#define NTOT 90000
#define NVP  30080
#define NTOTP 90080
#define DIM 256
#define NHEAD 8

// ---------------- scratch layout (float units) ----------------
#define OFF_NUMVP  0ull
#define OFF_NUMVN  7680000ull
#define OFF_NUMCP  15360000ull
#define OFF_NUMCN  30720000ull
#define OFF_DENVP  46080000ull
#define OFF_DENVN  46320000ull
#define OFF_DENCP  46560000ull
#define OFF_DENCN  47040000ull
#define OFF_V1M    47520000ull      // 90080*256 fp32
#define OFF_TMPM   70580480ull      // 90080*256 fp32
#define OFF_B768   93640960ull      // 1024
#define OFF_BF     93642000ull      // bf16 area (bf16-element offsets)
#define B_XB    0ull                // 90000*256
#define B_PB    23040000ull         // 90000*512 [q|k]
#define B_VB    69120000ull         // 90000*256 v bf16 (compact)
#define B_X1B   92160000ull         // 90080*256
#define B_HID   115220480ull        // 90080*256
#define B_WQKV  138280960ull        // 256*768
#define B_FFNW  138477568ull        // 4*65536
// bf16 total 138,739,712 -> 69,369,856 floats
#define SCRATCH_TOTAL 163011856ull

__device__ float g_scratch[SCRATCH_TOTAL];

// ---------------- helpers ----------------
__device__ __forceinline__ void ldsm_x4(uint32_t* r, uint32_t saddr) {
    asm volatile("ldmatrix.sync.aligned.m8n8.x4.shared.b16 {%0,%1,%2,%3}, [%4];"
                 : "=r"(r[0]), "=r"(r[1]), "=r"(r[2]), "=r"(r[3]) : "r"(saddr));
}
__device__ __forceinline__ void ldsm_x4_trans(uint32_t* r, uint32_t saddr) {
    asm volatile("ldmatrix.sync.aligned.m8n8.x4.trans.shared.b16 {%0,%1,%2,%3}, [%4];"
                 : "=r"(r[0]), "=r"(r[1]), "=r"(r[2]), "=r"(r[3]) : "r"(saddr));
}
__device__ __forceinline__ void mma_bf16(float* d, const uint32_t* a, const uint32_t* b) {
    asm volatile(
        "mma.sync.aligned.m16n8k16.row.col.f32.bf16.bf16.f32 "
        "{%0,%1,%2,%3}, {%4,%5,%6,%7}, {%8,%9}, {%0,%1,%2,%3};"
        : "+f"(d[0]), "+f"(d[1]), "+f"(d[2]), "+f"(d[3])
        : "r"(a[0]), "r"(a[1]), "r"(a[2]), "r"(a[3]),
          "r"(b[0]), "r"(b[1]));
}
__device__ __forceinline__ void red_add_v4(float* addr, float4 v) {
    asm volatile("red.global.add.v4.f32 [%0], {%1,%2,%3,%4};"
                 :: "l"(addr), "f"(v.x), "f"(v.y), "f"(v.z), "f"(v.w) : "memory");
}
__device__ __forceinline__ void cp_async16(uint32_t saddr, const void* gaddr, int src_size) {
    asm volatile("cp.async.cg.shared.global [%0], [%1], 16, %2;"
                 :: "r"(saddr), "l"(gaddr), "r"(src_size));
}
#define CP_COMMIT() asm volatile("cp.async.commit_group;" ::: "memory")
#define CP_WAIT0()  asm volatile("cp.async.wait_group 0;" ::: "memory")

// ---------------- conversion kernels ----------------
__global__ void cvt_x(const float* __restrict__ v, const float* __restrict__ c,
                      __nv_bfloat16* __restrict__ d) {
    int i = blockIdx.x * blockDim.x + threadIdx.x;
    if (i >= NTOT * 64) return;
    const float* src = (i < NVAR * 64) ? v : c - (size_t)NVAR * 256;
    float4 t = ((const float4*)src)[i];
    __nv_bfloat162 lo = __float22bfloat162_rn(make_float2(t.x, t.y));
    __nv_bfloat162 hi = __float22bfloat162_rn(make_float2(t.z, t.w));
    ((uint2*)d)[i] = make_uint2(*(uint32_t*)&lo, *(uint32_t*)&hi);
}
__global__ void cvt_w4(const float* __restrict__ w1, const float* __restrict__ w2,
                       const float* __restrict__ w3, const float* __restrict__ w4,
                       __nv_bfloat16* __restrict__ dst) {
    int i = blockIdx.x * blockDim.x + threadIdx.x;
    if (i >= 65536) return;
    int which = i >> 14;
    int j = i & 16383;
    const float* src = (which == 0) ? w1 : (which == 1) ? w2 : (which == 2) ? w3 : w4;
    float4 t = ((const float4*)src)[j];
    __nv_bfloat162 lo = __float22bfloat162_rn(make_float2(t.x, t.y));
    __nv_bfloat162 hi = __float22bfloat162_rn(make_float2(t.z, t.w));
    ((uint2*)(dst + (size_t)which * 65536))[j] = make_uint2(*(uint32_t*)&lo, *(uint32_t*)&hi);
}
__global__ void build_wqkv(const float* __restrict__ Wq, const float* __restrict__ Wkv,
                           __nv_bfloat16* __restrict__ dst) {
    int i = blockIdx.x * blockDim.x + threadIdx.x;
    if (i >= 256 * 768) return;
    int k = i / 768, j = i % 768;
    float val = (j < 256) ? Wq[k * 256 + j] : Wkv[k * 512 + (j - 256)];
    dst[i] = __float2bfloat16(val);
}
__global__ void build_bias768(const float* __restrict__ bq, const float* __restrict__ bkv,
                              float* __restrict__ dst) {
    int j = blockIdx.x * blockDim.x + threadIdx.x;
    if (j < 768) dst[j] = (j < 256) ? bq[j] : bkv[j - 256];
}

// ---------------- bf16 tensor-core GEMM, 128x128 tile, cp.async, split weights ----------------
// Outputs: fp32 C for cols>=cfrom (stride cs, col offset -cfrom);
//          bf16 Cb for cols<cbto (stride cbs);
//          bf16 Cb2 for cols>=c2from (stride c2s, col offset -c2from).
#define BM 128
#define BN 128
#define BK 32
#define ASTR 40
#define BSTR 136

__global__ __launch_bounds__(256, 2) void tgemm(
    const __nv_bfloat16* __restrict__ A, int lda,
    const __nv_bfloat16* __restrict__ W1, const __nv_bfloat16* __restrict__ W2, int nsplit,
    const float* __restrict__ bias1, const float* __restrict__ bias2,
    float* __restrict__ C, int cfrom, int cs,
    __nv_bfloat16* __restrict__ Cb, int cbto, int cbs,
    __nv_bfloat16* __restrict__ Cb2, int c2from, int c2s,
    int N, int M, int gelu)
{
    __shared__ __nv_bfloat16 As[2][BM * ASTR];
    __shared__ __nv_bfloat16 Ws[2][BK * BSTR];

    int tid = threadIdx.x;
    int lane = tid & 31;
    int warp = tid >> 5;
    int wm = (warp & 3) * 32;
    int wn = (warp >> 2) * 64;
    int bm = blockIdx.y * BM;
    int bn = blockIdx.x * BN;

    bool second = (W2 != nullptr) && (bm >= nsplit);
    const __nv_bfloat16* W = second ? W2 : W1;
    const float* bias = second ? bias2 : bias1;

    uint32_t as_base = (uint32_t)__cvta_generic_to_shared(&As[0][0]);
    uint32_t ws_base = (uint32_t)__cvta_generic_to_shared(&Ws[0][0]);
    const uint32_t as_sz = BM * ASTR * 2;
    const uint32_t ws_sz = BK * BSTR * 2;

    int a_row[2], a_col[2], w_row[2], w_col[2];
    uint32_t a_dst[2], w_dst[2];
    #pragma unroll
    for (int i = 0; i < 2; i++) {
        int g = tid + i * 256;
        a_row[i] = (tid * 2 + i) >> 2;
        a_col[i] = ((tid * 2 + i) & 3) * 8;
        w_row[i] = g >> 4;
        w_col[i] = (g & 15) * 8;
        a_dst[i] = as_base + (uint32_t)(a_row[i] * ASTR + a_col[i]) * 2;
        w_dst[i] = ws_base + (uint32_t)(w_row[i] * BSTR + w_col[i]) * 2;
    }

    float acc[2][8][4];
    #pragma unroll
    for (int mt = 0; mt < 2; mt++)
        #pragma unroll
        for (int nt = 0; nt < 8; nt++)
            #pragma unroll
            for (int i = 0; i < 4; i++) acc[mt][nt][i] = 0.0f;

    int a_r = lane & 15;
    int a_c = (lane >> 4) * 8;

    #pragma unroll
    for (int i = 0; i < 2; i++) {
        int gr = bm + a_row[i];
        cp_async16(a_dst[i], &A[(size_t)gr * lda + a_col[i]], (gr < N) ? 16 : 0);
        cp_async16(w_dst[i], &W[(size_t)w_row[i] * M + bn + w_col[i]], 16);
    }
    CP_COMMIT();
    CP_WAIT0();
    __syncthreads();

    for (int s = 0; s < 8; s++) {
        int cur = s & 1, nxt = cur ^ 1;
        if (s < 7) {
            int k0 = (s + 1) * BK;
            #pragma unroll
            for (int i = 0; i < 2; i++) {
                int gr = bm + a_row[i];
                cp_async16(a_dst[i] + nxt * as_sz,
                           &A[(size_t)gr * lda + k0 + a_col[i]], (gr < N) ? 16 : 0);
                cp_async16(w_dst[i] + nxt * ws_sz,
                           &W[(size_t)(k0 + w_row[i]) * M + bn + w_col[i]], 16);
            }
            CP_COMMIT();
        }

        uint32_t asb = as_base + cur * as_sz;
        uint32_t wsb = ws_base + cur * ws_sz;
        #pragma unroll
        for (int ks = 0; ks < 2; ks++) {
            int kb = ks * 16;
            uint32_t af[2][4], bf[4][4];
            #pragma unroll
            for (int mt = 0; mt < 2; mt++) {
                int row = wm + mt * 16 + a_r;
                int col = kb + a_c;
                ldsm_x4(af[mt], asb + (uint32_t)(row * ASTR + col) * 2);
            }
            #pragma unroll
            for (int p = 0; p < 4; p++) {
                int row = kb + (lane & 15);
                int col = wn + p * 16 + (lane >> 4) * 8;
                ldsm_x4_trans(bf[p], wsb + (uint32_t)(row * BSTR + col) * 2);
            }
            #pragma unroll
            for (int mt = 0; mt < 2; mt++)
                #pragma unroll
                for (int nt = 0; nt < 8; nt++)
                    mma_bf16(acc[mt][nt], af[mt], &bf[nt >> 1][(nt & 1) * 2]);
        }

        if (s < 7) {
            CP_WAIT0();
            __syncthreads();
        }
    }

    #pragma unroll
    for (int mt = 0; mt < 2; mt++) {
        int r0 = bm + wm + mt * 16 + (lane >> 2);
        #pragma unroll
        for (int nt = 0; nt < 8; nt++) {
            int cb = bn + wn + nt * 8 + (lane & 3) * 2;
            float b0 = bias[cb], b1 = bias[cb + 1];
            float2 lo = make_float2(acc[mt][nt][0] + b0, acc[mt][nt][1] + b1);
            float2 hi = make_float2(acc[mt][nt][2] + b0, acc[mt][nt][3] + b1);
            if (gelu) {
                lo.x = 0.5f * lo.x * (1.0f + erff(lo.x * 0.70710678118654752f));
                lo.y = 0.5f * lo.y * (1.0f + erff(lo.y * 0.70710678118654752f));
                hi.x = 0.5f * hi.x * (1.0f + erff(hi.x * 0.70710678118654752f));
                hi.y = 0.5f * hi.y * (1.0f + erff(hi.y * 0.70710678118654752f));
            }
            if (C && cb >= cfrom) {
                if (r0 < N)     *(float2*)&C[(size_t)r0 * cs + cb - cfrom] = lo;
                if (r0 + 8 < N) *(float2*)&C[(size_t)(r0 + 8) * cs + cb - cfrom] = hi;
            }
            if (Cb && cb < cbto) {
                __nv_bfloat162 blo = __float22bfloat162_rn(lo);
                __nv_bfloat162 bhi = __float22bfloat162_rn(hi);
                if (r0 < N)     *(__nv_bfloat162*)&Cb[(size_t)r0 * cbs + cb] = blo;
                if (r0 + 8 < N) *(__nv_bfloat162*)&Cb[(size_t)(r0 + 8) * cbs + cb] = bhi;
            }
            if (Cb2 && cb >= c2from) {
                __nv_bfloat162 blo = __float22bfloat162_rn(lo);
                __nv_bfloat162 bhi = __float22bfloat162_rn(hi);
                if (r0 < N)     *(__nv_bfloat162*)&Cb2[(size_t)r0 * c2s + cb - c2from] = blo;
                if (r0 + 8 < N) *(__nv_bfloat162*)&Cb2[(size_t)(r0 + 8) * c2s + cb - c2from] = bhi;
            }
        }
    }
}

// ---------------- edge attention: one side, BOTH polarities; bf16 v ----------------
// lane owns dims [lane*8, lane*8+8); head = lane>>2 for both score and value.
__global__ void edge_attn2(
    const __nv_bfloat16* __restrict__ Qb,
    const __nv_bfloat16* __restrict__ KVb,
    const __nv_bfloat16* __restrict__ Vb,   // compact bf16, stride 256
    const int* __restrict__ adj_p, const int* __restrict__ adj_n,
    int E, int qSecond,
    float* __restrict__ numP, float* __restrict__ denP,
    float* __restrict__ numN, float* __restrict__ denN)
{
    int gw = (int)(((size_t)blockIdx.x * blockDim.x + threadIdx.x) >> 5);
    int lane = threadIdx.x & 31;
    if (gw >= 2 * E) return;
    int pol = gw >= E;
    int e = gw - (pol ? E : 0);
    const int* adj = pol ? adj_n : adj_p;
    int s, t;
    if (qSecond) { s = adj[E + e]; t = adj[e]; }
    else         { s = adj[e];     t = adj[E + e]; }
    float* num = pol ? numN : numP;
    float* den = pol ? denN : denP;

    uint4 qu = *(const uint4*)&Qb[(size_t)s * 512 + lane * 8];
    uint4 ku = *(const uint4*)&KVb[(size_t)t * 512 + 256 + lane * 8];
    float p = 0.0f;
    {
        const __nv_bfloat162* qp = (const __nv_bfloat162*)&qu;
        const __nv_bfloat162* kp = (const __nv_bfloat162*)&ku;
        #pragma unroll
        for (int i = 0; i < 4; i++) {
            float2 qf = __bfloat1622float2(qp[i]);
            float2 kf = __bfloat1622float2(kp[i]);
            p += qf.x * kf.x + qf.y * kf.y;
        }
    }
    p += __shfl_xor_sync(0xffffffffu, p, 1);
    p += __shfl_xor_sync(0xffffffffu, p, 2);
    float ew = __expf(p * 0.17677669529663687f);   // this lane's head = lane>>2

    if ((lane & 3) == 0)
        atomicAdd(&den[(size_t)s * NHEAD + (lane >> 2)], ew);

    uint4 vu = *(const uint4*)&Vb[(size_t)t * 256 + lane * 8];
    const __nv_bfloat162* vp = (const __nv_bfloat162*)&vu;
    float2 v0 = __bfloat1622float2(vp[0]);
    float2 v1 = __bfloat1622float2(vp[1]);
    float2 v2 = __bfloat1622float2(vp[2]);
    float2 v3 = __bfloat1622float2(vp[3]);
    float* base = &num[(size_t)s * 256 + lane * 8];
    red_add_v4(base,     make_float4(ew * v0.x, ew * v0.y, ew * v1.x, ew * v1.y));
    red_add_v4(base + 4, make_float4(ew * v2.x, ew * v2.y, ew * v3.x, ew * v3.y));
}

// ---------------- merged attention LN ----------------
__global__ void ln_att_m(const float* __restrict__ xv, const float* __restrict__ xc,
                         const float* __restrict__ nVp, const float* __restrict__ dVp,
                         const float* __restrict__ nVn, const float* __restrict__ dVn,
                         const float* __restrict__ nCp, const float* __restrict__ dCp,
                         const float* __restrict__ nCn, const float* __restrict__ dCn,
                         const float* __restrict__ gv, const float* __restrict__ bv,
                         const float* __restrict__ gc, const float* __restrict__ bc,
                         float* __restrict__ y, __nv_bfloat16* __restrict__ yb)
{
    int gr = blockIdx.x * (blockDim.x >> 5) + (threadIdx.x >> 5);
    int lane = threadIdx.x & 31;
    if (gr >= NTOT) return;
    bool isv = gr < NVAR;
    int node = isv ? gr : gr - NVAR;
    const float* x  = isv ? xv : xc;
    const float* np_ = isv ? nVp : nCp;
    const float* dp  = isv ? dVp : dCp;
    const float* nn_ = isv ? nVn : nCn;
    const float* dn  = isv ? dVn : dCn;
    const float* g = isv ? gv : gc;
    const float* b = isv ? bv : bc;
    size_t orow = isv ? (size_t)gr : (size_t)NVP + node;

    float vals[8];
    float s = 0.0f;
    #pragma unroll
    for (int i = 0; i < 8; i++) {
        size_t idx = (size_t)node * 256 + i * 32 + lane;
        float a = x[idx];
        float dpi = dp[(size_t)node * NHEAD + i];
        float dni = dn[(size_t)node * NHEAD + i];
        if (dpi > 0.0f) a += np_[idx] / dpi;
        if (dni > 0.0f) a += nn_[idx] / dni;
        vals[i] = a;
        s += a;
    }
    #pragma unroll
    for (int o = 16; o > 0; o >>= 1) s += __shfl_xor_sync(0xffffffffu, s, o);
    float mean = s * (1.0f / 256.0f);
    float v2 = 0.0f;
    #pragma unroll
    for (int i = 0; i < 8; i++) { float d = vals[i] - mean; v2 += d * d; }
    #pragma unroll
    for (int o = 16; o > 0; o >>= 1) v2 += __shfl_xor_sync(0xffffffffu, v2, o);
    float rstd = rsqrtf(v2 * (1.0f / 256.0f) + 1e-5f);
    #pragma unroll
    for (int i = 0; i < 8; i++) {
        int cidx = i * 32 + lane;
        float out = (vals[i] - mean) * rstd * g[cidx] + b[cidx];
        y[orow * 256 + cidx] = out;
        yb[orow * 256 + cidx] = __float2bfloat16(out);
    }
}

// ---------------- merged final LN ----------------
__global__ void ln_add_m(const float* __restrict__ x, const float* __restrict__ a,
                         const float* __restrict__ gv, const float* __restrict__ bv,
                         const float* __restrict__ gc, const float* __restrict__ bc,
                         float* __restrict__ out_v, float* __restrict__ out_c)
{
    int gr = blockIdx.x * (blockDim.x >> 5) + (threadIdx.x >> 5);
    int lane = threadIdx.x & 31;
    if (gr >= NTOT) return;
    bool isv = gr < NVAR;
    int node = isv ? gr : gr - NVAR;
    size_t brow = isv ? (size_t)gr : (size_t)NVP + node;
    const float* g = isv ? gv : gc;
    const float* b = isv ? bv : bc;
    float* y = isv ? out_v : out_c;

    float vals[8];
    float s = 0.0f;
    #pragma unroll
    for (int i = 0; i < 8; i++) {
        size_t idx = brow * 256 + i * 32 + lane;
        vals[i] = x[idx] + a[idx];
        s += vals[i];
    }
    #pragma unroll
    for (int o = 16; o > 0; o >>= 1) s += __shfl_xor_sync(0xffffffffu, s, o);
    float mean = s * (1.0f / 256.0f);
    float v2 = 0.0f;
    #pragma unroll
    for (int i = 0; i < 8; i++) { float d = vals[i] - mean; v2 += d * d; }
    #pragma unroll
    for (int o = 16; o > 0; o >>= 1) v2 += __shfl_xor_sync(0xffffffffu, v2, o);
    float rstd = rsqrtf(v2 * (1.0f / 256.0f) + 1e-5f);
    #pragma unroll
    for (int i = 0; i < 8; i++) {
        int cidx = i * 32 + lane;
        y[(size_t)node * 256 + cidx] = (vals[i] - mean) * rstd * g[cidx] + b[cidx];
    }
}

extern "C" void kernel_launch(void* const* d_in, const int* in_sizes, int n_in,
                              void* d_out, int out_size)
{
    const float* v       = (const float*)d_in[0];
    const float* c       = (const float*)d_in[1];
    const int*   adj_pos = (const int*)d_in[2];
    const int*   adj_neg = (const int*)d_in[3];
    const float* Wq      = (const float*)d_in[4];
    const float* bq      = (const float*)d_in[5];
    const float* Wkv     = (const float*)d_in[6];
    const float* bkv     = (const float*)d_in[7];
    const float* fvw1    = (const float*)d_in[8];
    const float* fvb1    = (const float*)d_in[9];
    const float* fvw2    = (const float*)d_in[10];
    const float* fvb2    = (const float*)d_in[11];
    const float* fcw1    = (const float*)d_in[12];
    const float* fcb1    = (const float*)d_in[13];
    const float* fcw2    = (const float*)d_in[14];
    const float* fcb2    = (const float*)d_in[15];
    const float* lavg    = (const float*)d_in[16];
    const float* lavb    = (const float*)d_in[17];
    const float* lfvg    = (const float*)d_in[18];
    const float* lfvb    = (const float*)d_in[19];
    const float* lacg    = (const float*)d_in[20];
    const float* lacb    = (const float*)d_in[21];
    const float* lfcg    = (const float*)d_in[22];
    const float* lfcb    = (const float*)d_in[23];

    int E = in_sizes[2] / 2;

    float* buf;
    cudaGetSymbolAddress((void**)&buf, g_scratch);

    float* numVp = buf + OFF_NUMVP;
    float* numVn = buf + OFF_NUMVN;
    float* numCp = buf + OFF_NUMCP;
    float* numCn = buf + OFF_NUMCN;
    float* denVp = buf + OFF_DENVP;
    float* denVn = buf + OFF_DENVN;
    float* denCp = buf + OFF_DENCP;
    float* denCn = buf + OFF_DENCN;
    float* v1m   = buf + OFF_V1M;
    float* tmpm  = buf + OFF_TMPM;
    float* b768  = buf + OFF_B768;

    __nv_bfloat16* bfb   = (__nv_bfloat16*)(buf + OFF_BF);
    __nv_bfloat16* xb    = bfb + B_XB;
    __nv_bfloat16* pb    = bfb + B_PB;     // [q|k] 90000 x 512
    __nv_bfloat16* vb    = bfb + B_VB;     // v bf16 90000 x 256
    __nv_bfloat16* x1b   = bfb + B_X1B;
    __nv_bfloat16* hidb  = bfb + B_HID;
    __nv_bfloat16* wqkvb = bfb + B_WQKV;
    __nv_bfloat16* ffnw  = bfb + B_FFNW;
    __nv_bfloat16* fvw1b = ffnw;
    __nv_bfloat16* fvw2b = ffnw + 65536;
    __nv_bfloat16* fcw1b = ffnw + 131072;
    __nv_bfloat16* fcw2b = ffnw + 196608;

    __nv_bfloat16* pvb = pb;
    __nv_bfloat16* pcb = pb + (size_t)NVAR * 512;
    __nv_bfloat16* vbv = vb;
    __nv_bfloat16* vbc = vb + (size_t)NVAR * 256;

    float* out_v = (float*)d_out;
    float* out_c = out_v + (size_t)NVAR * DIM;

    // ---- conversions ----
    cvt_x<<<(NTOT * 64 + 255) / 256, 256>>>(v, c, xb);
    cvt_w4<<<256, 256>>>(fvw1, fvw2, fcw1, fcw2, ffnw);
    build_wqkv<<<768, 256>>>(Wq, Wkv, wqkvb);
    build_bias768<<<3, 256>>>(bq, bkv, b768);

    cudaMemsetAsync(numVp, 0, (size_t)OFF_V1M * sizeof(float), 0);

    // ---- merged projection: 90000 x 768, bf16 [q|k] + bf16 v (compact) ----
    {
        dim3 grid(768 / BN, (NTOT + BM - 1) / BM);
        tgemm<<<grid, 256>>>(xb, 256, wqkvb, nullptr, 0, b768, b768,
                             nullptr, 0, 0,
                             pb, 512, 512,
                             vb, 512, 256,
                             NTOT, 768, 0);
    }

    // ---- edge attention: one launch per side, both polarities ----
    int eblocks2 = (int)(((size_t)2 * E * 32 + 255) / 256);
    edge_attn2<<<eblocks2, 256>>>(pvb, pcb, vbc, adj_pos, adj_neg, E, 1,
                                  numVp, denVp, numVn, denVn);
    edge_attn2<<<eblocks2, 256>>>(pcb, pvb, vbv, adj_pos, adj_neg, E, 0,
                                  numCp, denCp, numCn, denCn);

    // ---- merged attention LN ----
    ln_att_m<<<(NTOT + 7) / 8, 256>>>(v, c,
                                      numVp, denVp, numVn, denVn,
                                      numCp, denCp, numCn, denCn,
                                      lavg, lavb, lacg, lacb, v1m, x1b);

    // ---- merged FFN (split weights at row NVP) ----
    {
        dim3 grid(256 / BN, (NTOTP + BM - 1) / BM);
        tgemm<<<grid, 256>>>(x1b, 256, fvw1b, fcw1b, NVP, fvb1, fcb1,
                             nullptr, 1 << 30, 0,
                             hidb, 256, 256,
                             nullptr, 1 << 30, 0,
                             NTOTP, 256, 1);
        tgemm<<<grid, 256>>>(hidb, 256, fvw2b, fcw2b, NVP, fvb2, fcb2,
                             tmpm, 0, 256,
                             nullptr, 0, 0,
                             nullptr, 1 << 30, 0,
                             NTOTP, 256, 0);
    }

    // ---- merged final LN ----
    ln_add_m<<<(NTOT + 7) / 8, 256>>>(v1m, tmpm, lfvg, lfvb, lfcg, lfcb, out_v, out_c);
}

// round 14
// speedup vs baseline: 1.0835x; 1.0835x over previous
#include <cuda_runtime.h>
#include <cuda_bf16.h>
#include <math.h>
#include <stdint.h>

#define NVAR 30000
#define NCLS 60000
#define NTOT 90000
#define NVP  30080
#define NTOTP 90080
#define DIM 256
#define NHEAD 8

// ---------------- scratch layout (float units) ----------------
#define OFF_NUMVP  0ull
#define OFF_NUMVN  7680000ull
#define OFF_NUMCP  15360000ull
#define OFF_NUMCN  30720000ull
#define OFF_DENVP  46080000ull
#define OFF_DENVN  46320000ull
#define OFF_DENCP  46560000ull
#define OFF_DENCN  47040000ull
#define OFF_PVF    47520000ull      // 90000*256 fp32 v-part (compact)
#define OFF_V1M    70560000ull      // 90080*256 fp32
#define OFF_B768   93620480ull      // 1024
#define OFF_BF     93621504ull      // bf16 area (bf16-element offsets)
#define B_XB    0ull                // 90000*256
#define B_PB    23040000ull         // 90000*512 [q|k]
#define B_X1B   69120000ull         // 90080*256
#define B_HID   92180480ull         // 90080*256
#define B_TMPB  115240960ull        // 90080*256 (FFN2 out, bf16)
#define B_WQKV  138301440ull        // 256*768
#define B_FFNW  138498048ull        // 4*65536
// bf16 total 138,760,192 -> 69,380,096 floats
#define SCRATCH_TOTAL 163001600ull

__device__ float g_scratch[SCRATCH_TOTAL];

// ---------------- helpers ----------------
__device__ __forceinline__ void ldsm_x4(uint32_t* r, uint32_t saddr) {
    asm volatile("ldmatrix.sync.aligned.m8n8.x4.shared.b16 {%0,%1,%2,%3}, [%4];"
                 : "=r"(r[0]), "=r"(r[1]), "=r"(r[2]), "=r"(r[3]) : "r"(saddr));
}
__device__ __forceinline__ void ldsm_x4_trans(uint32_t* r, uint32_t saddr) {
    asm volatile("ldmatrix.sync.aligned.m8n8.x4.trans.shared.b16 {%0,%1,%2,%3}, [%4];"
                 : "=r"(r[0]), "=r"(r[1]), "=r"(r[2]), "=r"(r[3]) : "r"(saddr));
}
__device__ __forceinline__ void mma_bf16(float* d, const uint32_t* a, const uint32_t* b) {
    asm volatile(
        "mma.sync.aligned.m16n8k16.row.col.f32.bf16.bf16.f32 "
        "{%0,%1,%2,%3}, {%4,%5,%6,%7}, {%8,%9}, {%0,%1,%2,%3};"
        : "+f"(d[0]), "+f"(d[1]), "+f"(d[2]), "+f"(d[3])
        : "r"(a[0]), "r"(a[1]), "r"(a[2]), "r"(a[3]),
          "r"(b[0]), "r"(b[1]));
}
__device__ __forceinline__ void red_add_v4(float* addr, float4 v) {
    asm volatile("red.global.add.v4.f32 [%0], {%1,%2,%3,%4};"
                 :: "l"(addr), "f"(v.x), "f"(v.y), "f"(v.z), "f"(v.w) : "memory");
}
__device__ __forceinline__ void cp_async16(uint32_t saddr, const void* gaddr, int src_size) {
    asm volatile("cp.async.cg.shared.global [%0], [%1], 16, %2;"
                 :: "r"(saddr), "l"(gaddr), "r"(src_size));
}
#define CP_COMMIT() asm volatile("cp.async.commit_group;" ::: "memory")
#define CP_WAIT0()  asm volatile("cp.async.wait_group 0;" ::: "memory")

// ---------------- conversion kernels ----------------
__global__ void cvt_x(const float* __restrict__ v, const float* __restrict__ c,
                      __nv_bfloat16* __restrict__ d) {
    int i = blockIdx.x * blockDim.x + threadIdx.x;
    if (i >= NTOT * 64) return;
    const float* src = (i < NVAR * 64) ? v : c - (size_t)NVAR * 256;
    float4 t = ((const float4*)src)[i];
    __nv_bfloat162 lo = __float22bfloat162_rn(make_float2(t.x, t.y));
    __nv_bfloat162 hi = __float22bfloat162_rn(make_float2(t.z, t.w));
    ((uint2*)d)[i] = make_uint2(*(uint32_t*)&lo, *(uint32_t*)&hi);
}

// merged setup: blocks [0,256) cvt FFN weights; [256,1024) build wqkv; [1024,1027) bias
__global__ void setup_misc(const float* __restrict__ Wq, const float* __restrict__ Wkv,
                           const float* __restrict__ bq, const float* __restrict__ bkv,
                           const float* __restrict__ w1, const float* __restrict__ w2,
                           const float* __restrict__ w3, const float* __restrict__ w4,
                           __nv_bfloat16* __restrict__ wqkvb,
                           __nv_bfloat16* __restrict__ ffnw,
                           float* __restrict__ b768) {
    int blk = blockIdx.x;
    int tid = threadIdx.x;
    if (blk < 256) {
        int i = blk * 256 + tid;                // float4 index, 65536 total
        int which = i >> 14;
        int j = i & 16383;
        const float* src = (which == 0) ? w1 : (which == 1) ? w2 : (which == 2) ? w3 : w4;
        float4 t = ((const float4*)src)[j];
        __nv_bfloat162 lo = __float22bfloat162_rn(make_float2(t.x, t.y));
        __nv_bfloat162 hi = __float22bfloat162_rn(make_float2(t.z, t.w));
        ((uint2*)(ffnw + (size_t)which * 65536))[j] =
            make_uint2(*(uint32_t*)&lo, *(uint32_t*)&hi);
    } else if (blk < 1024) {
        int i = (blk - 256) * 256 + tid;        // 196608 total
        int k = i / 768, j = i % 768;
        float val = (j < 256) ? Wq[k * 256 + j] : Wkv[k * 512 + (j - 256)];
        wqkvb[i] = __float2bfloat16(val);
    } else {
        int j = (blk - 1024) * 256 + tid;
        if (j < 768) b768[j] = (j < 256) ? bq[j] : bkv[j - 256];
    }
}

// ---------------- bf16 tensor-core GEMM, 128x128 tile, cp.async, split weights ----------------
#define BM 128
#define BN 128
#define BK 32
#define ASTR 40
#define BSTR 136

__global__ __launch_bounds__(256, 2) void tgemm(
    const __nv_bfloat16* __restrict__ A, int lda,
    const __nv_bfloat16* __restrict__ W1, const __nv_bfloat16* __restrict__ W2, int nsplit,
    const float* __restrict__ bias1, const float* __restrict__ bias2,
    float* __restrict__ C, int cfrom, int cs,
    __nv_bfloat16* __restrict__ Cb, int cbto, int cbs,
    int N, int M, int gelu)
{
    __shared__ __nv_bfloat16 As[2][BM * ASTR];
    __shared__ __nv_bfloat16 Ws[2][BK * BSTR];

    int tid = threadIdx.x;
    int lane = tid & 31;
    int warp = tid >> 5;
    int wm = (warp & 3) * 32;
    int wn = (warp >> 2) * 64;
    int bm = blockIdx.y * BM;
    int bn = blockIdx.x * BN;

    bool second = (W2 != nullptr) && (bm >= nsplit);
    const __nv_bfloat16* W = second ? W2 : W1;
    const float* bias = second ? bias2 : bias1;

    uint32_t as_base = (uint32_t)__cvta_generic_to_shared(&As[0][0]);
    uint32_t ws_base = (uint32_t)__cvta_generic_to_shared(&Ws[0][0]);
    const uint32_t as_sz = BM * ASTR * 2;
    const uint32_t ws_sz = BK * BSTR * 2;

    int a_row[2], a_col[2], w_row[2], w_col[2];
    uint32_t a_dst[2], w_dst[2];
    #pragma unroll
    for (int i = 0; i < 2; i++) {
        int g = tid + i * 256;
        a_row[i] = (tid * 2 + i) >> 2;
        a_col[i] = ((tid * 2 + i) & 3) * 8;
        w_row[i] = g >> 4;
        w_col[i] = (g & 15) * 8;
        a_dst[i] = as_base + (uint32_t)(a_row[i] * ASTR + a_col[i]) * 2;
        w_dst[i] = ws_base + (uint32_t)(w_row[i] * BSTR + w_col[i]) * 2;
    }

    float acc[2][8][4];
    #pragma unroll
    for (int mt = 0; mt < 2; mt++)
        #pragma unroll
        for (int nt = 0; nt < 8; nt++)
            #pragma unroll
            for (int i = 0; i < 4; i++) acc[mt][nt][i] = 0.0f;

    int a_r = lane & 15;
    int a_c = (lane >> 4) * 8;

    #pragma unroll
    for (int i = 0; i < 2; i++) {
        int gr = bm + a_row[i];
        cp_async16(a_dst[i], &A[(size_t)gr * lda + a_col[i]], (gr < N) ? 16 : 0);
        cp_async16(w_dst[i], &W[(size_t)w_row[i] * M + bn + w_col[i]], 16);
    }
    CP_COMMIT();
    CP_WAIT0();
    __syncthreads();

    for (int s = 0; s < 8; s++) {
        int cur = s & 1, nxt = cur ^ 1;
        if (s < 7) {
            int k0 = (s + 1) * BK;
            #pragma unroll
            for (int i = 0; i < 2; i++) {
                int gr = bm + a_row[i];
                cp_async16(a_dst[i] + nxt * as_sz,
                           &A[(size_t)gr * lda + k0 + a_col[i]], (gr < N) ? 16 : 0);
                cp_async16(w_dst[i] + nxt * ws_sz,
                           &W[(size_t)(k0 + w_row[i]) * M + bn + w_col[i]], 16);
            }
            CP_COMMIT();
        }

        uint32_t asb = as_base + cur * as_sz;
        uint32_t wsb = ws_base + cur * ws_sz;
        #pragma unroll
        for (int ks = 0; ks < 2; ks++) {
            int kb = ks * 16;
            uint32_t af[2][4], bf[4][4];
            #pragma unroll
            for (int mt = 0; mt < 2; mt++) {
                int row = wm + mt * 16 + a_r;
                int col = kb + a_c;
                ldsm_x4(af[mt], asb + (uint32_t)(row * ASTR + col) * 2);
            }
            #pragma unroll
            for (int p = 0; p < 4; p++) {
                int row = kb + (lane & 15);
                int col = wn + p * 16 + (lane >> 4) * 8;
                ldsm_x4_trans(bf[p], wsb + (uint32_t)(row * BSTR + col) * 2);
            }
            #pragma unroll
            for (int mt = 0; mt < 2; mt++)
                #pragma unroll
                for (int nt = 0; nt < 8; nt++)
                    mma_bf16(acc[mt][nt], af[mt], &bf[nt >> 1][(nt & 1) * 2]);
        }

        if (s < 7) {
            CP_WAIT0();
            __syncthreads();
        }
    }

    #pragma unroll
    for (int mt = 0; mt < 2; mt++) {
        int r0 = bm + wm + mt * 16 + (lane >> 2);
        #pragma unroll
        for (int nt = 0; nt < 8; nt++) {
            int cb = bn + wn + nt * 8 + (lane & 3) * 2;
            float b0 = bias[cb], b1 = bias[cb + 1];
            float2 lo = make_float2(acc[mt][nt][0] + b0, acc[mt][nt][1] + b1);
            float2 hi = make_float2(acc[mt][nt][2] + b0, acc[mt][nt][3] + b1);
            if (gelu) {
                lo.x = 0.5f * lo.x * (1.0f + erff(lo.x * 0.70710678118654752f));
                lo.y = 0.5f * lo.y * (1.0f + erff(lo.y * 0.70710678118654752f));
                hi.x = 0.5f * hi.x * (1.0f + erff(hi.x * 0.70710678118654752f));
                hi.y = 0.5f * hi.y * (1.0f + erff(hi.y * 0.70710678118654752f));
            }
            if (C && cb >= cfrom) {
                if (r0 < N)     *(float2*)&C[(size_t)r0 * cs + cb - cfrom] = lo;
                if (r0 + 8 < N) *(float2*)&C[(size_t)(r0 + 8) * cs + cb - cfrom] = hi;
            }
            if (Cb && cb < cbto) {
                __nv_bfloat162 blo = __float22bfloat162_rn(lo);
                __nv_bfloat162 bhi = __float22bfloat162_rn(hi);
                if (r0 < N)     *(__nv_bfloat162*)&Cb[(size_t)r0 * cbs + cb] = blo;
                if (r0 + 8 < N) *(__nv_bfloat162*)&Cb[(size_t)(r0 + 8) * cbs + cb] = bhi;
            }
        }
    }
}

// ---------------- edge attention: one side, BOTH polarities (fp32 v) ----------------
__global__ void edge_attn2(
    const __nv_bfloat16* __restrict__ Qb,
    const __nv_bfloat16* __restrict__ KVb,
    const float* __restrict__ Vf,          // compact fp32, stride 256
    const int* __restrict__ adj_p, const int* __restrict__ adj_n,
    int E, int qSecond,
    float* __restrict__ numP, float* __restrict__ denP,
    float* __restrict__ numN, float* __restrict__ denN)
{
    int gw = (int)(((size_t)blockIdx.x * blockDim.x + threadIdx.x) >> 5);
    int lane = threadIdx.x & 31;
    if (gw >= 2 * E) return;
    int pol = gw >= E;
    int e = gw - (pol ? E : 0);
    const int* adj = pol ? adj_n : adj_p;
    int s, t;
    if (qSecond) { s = adj[E + e]; t = adj[e]; }
    else         { s = adj[e];     t = adj[E + e]; }
    float* num = pol ? numN : numP;
    float* den = pol ? denN : denP;

    uint4 qu = *(const uint4*)&Qb[(size_t)s * 512 + lane * 8];
    uint4 ku = *(const uint4*)&KVb[(size_t)t * 512 + 256 + lane * 8];
    float p = 0.0f;
    {
        const __nv_bfloat162* qp = (const __nv_bfloat162*)&qu;
        const __nv_bfloat162* kp = (const __nv_bfloat162*)&ku;
        #pragma unroll
        for (int i = 0; i < 4; i++) {
            float2 qf = __bfloat1622float2(qp[i]);
            float2 kf = __bfloat1622float2(kp[i]);
            p += qf.x * kf.x + qf.y * kf.y;
        }
    }
    p += __shfl_xor_sync(0xffffffffu, p, 1);
    p += __shfl_xor_sync(0xffffffffu, p, 2);
    float ew = __expf(p * 0.17677669529663687f);   // this lane's head = lane>>2

    // den: gather 4 heads into lanes 0 and 16, issue 2 red.v4 instead of 8 scalar REDs
    {
        int base = lane & 16;
        float e0 = __shfl_sync(0xffffffffu, ew, base + 0);
        float e1 = __shfl_sync(0xffffffffu, ew, base + 4);
        float e2 = __shfl_sync(0xffffffffu, ew, base + 8);
        float e3 = __shfl_sync(0xffffffffu, ew, base + 12);
        if ((lane & 15) == 0)
            red_add_v4(&den[(size_t)s * NHEAD + (base >> 2)], make_float4(e0, e1, e2, e3));
    }

    #pragma unroll
    for (int ch = 0; ch < 2; ch++) {
        float ec = __shfl_sync(0xffffffffu, ew, 16 * ch + ((lane >> 3) << 2));
        float4 vv = *(const float4*)&Vf[(size_t)t * 256 + ch * 128 + lane * 4];
        red_add_v4(&num[(size_t)s * 256 + ch * 128 + lane * 4],
                   make_float4(ec * vv.x, ec * vv.y, ec * vv.z, ec * vv.w));
    }
}

// ---------------- merged attention LN ----------------
__global__ void ln_att_m(const float* __restrict__ xv, const float* __restrict__ xc,
                         const float* __restrict__ nVp, const float* __restrict__ dVp,
                         const float* __restrict__ nVn, const float* __restrict__ dVn,
                         const float* __restrict__ nCp, const float* __restrict__ dCp,
                         const float* __restrict__ nCn, const float* __restrict__ dCn,
                         const float* __restrict__ gv, const float* __restrict__ bv,
                         const float* __restrict__ gc, const float* __restrict__ bc,
                         float* __restrict__ y, __nv_bfloat16* __restrict__ yb)
{
    int gr = blockIdx.x * (blockDim.x >> 5) + (threadIdx.x >> 5);
    int lane = threadIdx.x & 31;
    if (gr >= NTOT) return;
    bool isv = gr < NVAR;
    int node = isv ? gr : gr - NVAR;
    const float* x  = isv ? xv : xc;
    const float* np_ = isv ? nVp : nCp;
    const float* dp  = isv ? dVp : dCp;
    const float* nn_ = isv ? nVn : nCn;
    const float* dn  = isv ? dVn : dCn;
    const float* g = isv ? gv : gc;
    const float* b = isv ? bv : bc;
    size_t orow = isv ? (size_t)gr : (size_t)NVP + node;

    float vals[8];
    float s = 0.0f;
    #pragma unroll
    for (int i = 0; i < 8; i++) {
        size_t idx = (size_t)node * 256 + i * 32 + lane;
        float a = x[idx];
        float dpi = dp[(size_t)node * NHEAD + i];
        float dni = dn[(size_t)node * NHEAD + i];
        if (dpi > 0.0f) a += np_[idx] / dpi;
        if (dni > 0.0f) a += nn_[idx] / dni;
        vals[i] = a;
        s += a;
    }
    #pragma unroll
    for (int o = 16; o > 0; o >>= 1) s += __shfl_xor_sync(0xffffffffu, s, o);
    float mean = s * (1.0f / 256.0f);
    float v2 = 0.0f;
    #pragma unroll
    for (int i = 0; i < 8; i++) { float d = vals[i] - mean; v2 += d * d; }
    #pragma unroll
    for (int o = 16; o > 0; o >>= 1) v2 += __shfl_xor_sync(0xffffffffu, v2, o);
    float rstd = rsqrtf(v2 * (1.0f / 256.0f) + 1e-5f);
    #pragma unroll
    for (int i = 0; i < 8; i++) {
        int cidx = i * 32 + lane;
        float out = (vals[i] - mean) * rstd * g[cidx] + b[cidx];
        y[orow * 256 + cidx] = out;
        yb[orow * 256 + cidx] = __float2bfloat16(out);
    }
}

// ---------------- merged final LN: y = LN(x + a_bf16) ----------------
__global__ void ln_add_m(const float* __restrict__ x, const __nv_bfloat16* __restrict__ a,
                         const float* __restrict__ gv, const float* __restrict__ bv,
                         const float* __restrict__ gc, const float* __restrict__ bc,
                         float* __restrict__ out_v, float* __restrict__ out_c)
{
    int gr = blockIdx.x * (blockDim.x >> 5) + (threadIdx.x >> 5);
    int lane = threadIdx.x & 31;
    if (gr >= NTOT) return;
    bool isv = gr < NVAR;
    int node = isv ? gr : gr - NVAR;
    size_t brow = isv ? (size_t)gr : (size_t)NVP + node;
    const float* g = isv ? gv : gc;
    const float* b = isv ? bv : bc;
    float* y = isv ? out_v : out_c;

    float vals[8];
    float s = 0.0f;
    #pragma unroll
    for (int i = 0; i < 8; i++) {
        size_t idx = brow * 256 + i * 32 + lane;
        vals[i] = x[idx] + __bfloat162float(a[idx]);
        s += vals[i];
    }
    #pragma unroll
    for (int o = 16; o > 0; o >>= 1) s += __shfl_xor_sync(0xffffffffu, s, o);
    float mean = s * (1.0f / 256.0f);
    float v2 = 0.0f;
    #pragma unroll
    for (int i = 0; i < 8; i++) { float d = vals[i] - mean; v2 += d * d; }
    #pragma unroll
    for (int o = 16; o > 0; o >>= 1) v2 += __shfl_xor_sync(0xffffffffu, v2, o);
    float rstd = rsqrtf(v2 * (1.0f / 256.0f) + 1e-5f);
    #pragma unroll
    for (int i = 0; i < 8; i++) {
        int cidx = i * 32 + lane;
        y[(size_t)node * 256 + cidx] = (vals[i] - mean) * rstd * g[cidx] + b[cidx];
    }
}

extern "C" void kernel_launch(void* const* d_in, const int* in_sizes, int n_in,
                              void* d_out, int out_size)
{
    const float* v       = (const float*)d_in[0];
    const float* c       = (const float*)d_in[1];
    const int*   adj_pos = (const int*)d_in[2];
    const int*   adj_neg = (const int*)d_in[3];
    const float* Wq      = (const float*)d_in[4];
    const float* bq      = (const float*)d_in[5];
    const float* Wkv     = (const float*)d_in[6];
    const float* bkv     = (const float*)d_in[7];
    const float* fvw1    = (const float*)d_in[8];
    const float* fvb1    = (const float*)d_in[9];
    const float* fvw2    = (const float*)d_in[10];
    const float* fvb2    = (const float*)d_in[11];
    const float* fcw1    = (const float*)d_in[12];
    const float* fcb1    = (const float*)d_in[13];
    const float* fcw2    = (const float*)d_in[14];
    const float* fcb2    = (const float*)d_in[15];
    const float* lavg    = (const float*)d_in[16];
    const float* lavb    = (const float*)d_in[17];
    const float* lfvg    = (const float*)d_in[18];
    const float* lfvb    = (const float*)d_in[19];
    const float* lacg    = (const float*)d_in[20];
    const float* lacb    = (const float*)d_in[21];
    const float* lfcg    = (const float*)d_in[22];
    const float* lfcb    = (const float*)d_in[23];

    int E = in_sizes[2] / 2;

    float* buf;
    cudaGetSymbolAddress((void**)&buf, g_scratch);

    float* numVp = buf + OFF_NUMVP;
    float* numVn = buf + OFF_NUMVN;
    float* numCp = buf + OFF_NUMCP;
    float* numCn = buf + OFF_NUMCN;
    float* denVp = buf + OFF_DENVP;
    float* denVn = buf + OFF_DENVN;
    float* denCp = buf + OFF_DENCP;
    float* denCn = buf + OFF_DENCN;
    float* pvf   = buf + OFF_PVF;
    float* v1m   = buf + OFF_V1M;
    float* b768  = buf + OFF_B768;

    __nv_bfloat16* bfb   = (__nv_bfloat16*)(buf + OFF_BF);
    __nv_bfloat16* xb    = bfb + B_XB;
    __nv_bfloat16* pb    = bfb + B_PB;
    __nv_bfloat16* x1b   = bfb + B_X1B;
    __nv_bfloat16* hidb  = bfb + B_HID;
    __nv_bfloat16* tmpb  = bfb + B_TMPB;
    __nv_bfloat16* wqkvb = bfb + B_WQKV;
    __nv_bfloat16* ffnw  = bfb + B_FFNW;
    __nv_bfloat16* fvw1b = ffnw;
    __nv_bfloat16* fvw2b = ffnw + 65536;
    __nv_bfloat16* fcw1b = ffnw + 131072;
    __nv_bfloat16* fcw2b = ffnw + 196608;

    __nv_bfloat16* pvb = pb;
    __nv_bfloat16* pcb = pb + (size_t)NVAR * 512;
    float* vfv = pvf;
    float* vfc = pvf + (size_t)NVAR * 256;

    float* out_v = (float*)d_out;
    float* out_c = out_v + (size_t)NVAR * DIM;

    // ---- conversions ----
    cvt_x<<<(NTOT * 64 + 255) / 256, 256>>>(v, c, xb);
    setup_misc<<<1027, 256>>>(Wq, Wkv, bq, bkv, fvw1, fvw2, fcw1, fcw2,
                              wqkvb, ffnw, b768);

    cudaMemsetAsync(numVp, 0, (size_t)OFF_PVF * sizeof(float), 0);

    // ---- merged projection: 90000 x 768, bf16 [q|k] + compact fp32 v ----
    {
        dim3 grid(768 / BN, (NTOT + BM - 1) / BM);
        tgemm<<<grid, 256>>>(xb, 256, wqkvb, nullptr, 0, b768, b768,
                             pvf, 512, 256, pb, 512, 512, NTOT, 768, 0);
    }

    // ---- edge attention: one launch per side, both polarities ----
    int eblocks2 = (int)(((size_t)2 * E * 32 + 255) / 256);
    edge_attn2<<<eblocks2, 256>>>(pvb, pcb, vfc, adj_pos, adj_neg, E, 1,
                                  numVp, denVp, numVn, denVn);
    edge_attn2<<<eblocks2, 256>>>(pcb, pvb, vfv, adj_pos, adj_neg, E, 0,
                                  numCp, denCp, numCn, denCn);

    // ---- merged attention LN ----
    ln_att_m<<<(NTOT + 7) / 8, 256>>>(v, c,
                                      numVp, denVp, numVn, denVn,
                                      numCp, denCp, numCn, denCn,
                                      lavg, lavb, lacg, lacb, v1m, x1b);

    // ---- merged FFN (split weights at row NVP); FFN2 out bf16 ----
    {
        dim3 grid(256 / BN, (NTOTP + BM - 1) / BM);
        tgemm<<<grid, 256>>>(x1b, 256, fvw1b, fcw1b, NVP, fvb1, fcb1,
                             nullptr, 1 << 30, 0, hidb, 256, 256, NTOTP, 256, 1);
        tgemm<<<grid, 256>>>(hidb, 256, fvw2b, fcw2b, NVP, fvb2, fcb2,
                             nullptr, 1 << 30, 0, tmpb, 256, 256, NTOTP, 256, 0);
    }

    // ---- merged final LN ----
    ln_add_m<<<(NTOT + 7) / 8, 256>>>(v1m, tmpb, lfvg, lfvb, lfcg, lfcb, out_v, out_c);
}

// round 15
// speedup vs baseline: 1.3076x; 1.2069x over previous
#include <cuda_runtime.h>
#include <cuda_bf16.h>
#include <math.h>
#include <stdint.h>

#define NVAR 30000
#define NCLS 60000
#define NTOT 90000
#define NVP  30080
#define NTOTP 90080
#define DIM 256
#define NHEAD 8
#define NSEG (2 * NVAR + 2 * NCLS)     // 180000 CSR segments

// ---------------- scratch layout (float units) ----------------
#define OFF_ATT    0ull             // 90000*256 fp32 (v nodes then c nodes)
#define OFF_V1M    23040000ull      // 90080*256 fp32
#define OFF_B768   46100480ull      // 1024
#define OFF_IDX    46101504ull      // int area: deg, excl, cur, bsum, slots
#define IDX_DEG    0
#define IDX_EXCL   180000
#define IDX_CUR    360000
#define IDX_BSUM   540000           // 256
#define IDX_SLOTS  540256           // 480000
#define IDX_TOTAL  1020256
#define OFF_BF     47121760ull      // bf16 area (bf16-element offsets)
#define B_XB    0ull                // 90000*256
#define B_PB    23040000ull         // 90000*512 [q|k]
#define B_X1B   69120000ull         // 90080*256
#define B_HID   92180480ull
#define B_TMPB  115240960ull
#define B_WQKV  138301440ull        // 256*768
#define B_FFNW  138498048ull        // 4*65536
// bf16 total 138,760,192 -> 69,380,096 floats
// still need fp32 v-part:
#define OFF_PVF    116501856ull     // 90000*256 fp32
#define SCRATCH_TOTAL 139541856ull

__device__ float g_scratch[SCRATCH_TOTAL];

// ---------------- helpers ----------------
__device__ __forceinline__ void ldsm_x4(uint32_t* r, uint32_t saddr) {
    asm volatile("ldmatrix.sync.aligned.m8n8.x4.shared.b16 {%0,%1,%2,%3}, [%4];"
                 : "=r"(r[0]), "=r"(r[1]), "=r"(r[2]), "=r"(r[3]) : "r"(saddr));
}
__device__ __forceinline__ void ldsm_x4_trans(uint32_t* r, uint32_t saddr) {
    asm volatile("ldmatrix.sync.aligned.m8n8.x4.trans.shared.b16 {%0,%1,%2,%3}, [%4];"
                 : "=r"(r[0]), "=r"(r[1]), "=r"(r[2]), "=r"(r[3]) : "r"(saddr));
}
__device__ __forceinline__ void mma_bf16(float* d, const uint32_t* a, const uint32_t* b) {
    asm volatile(
        "mma.sync.aligned.m16n8k16.row.col.f32.bf16.bf16.f32 "
        "{%0,%1,%2,%3}, {%4,%5,%6,%7}, {%8,%9}, {%0,%1,%2,%3};"
        : "+f"(d[0]), "+f"(d[1]), "+f"(d[2]), "+f"(d[3])
        : "r"(a[0]), "r"(a[1]), "r"(a[2]), "r"(a[3]),
          "r"(b[0]), "r"(b[1]));
}
__device__ __forceinline__ void cp_async16(uint32_t saddr, const void* gaddr, int src_size) {
    asm volatile("cp.async.cg.shared.global [%0], [%1], 16, %2;"
                 :: "r"(saddr), "l"(gaddr), "r"(src_size));
}
#define CP_COMMIT() asm volatile("cp.async.commit_group;" ::: "memory")
#define CP_WAIT0()  asm volatile("cp.async.wait_group 0;" ::: "memory")

// ---------------- conversion / setup kernels ----------------
__global__ void cvt_x(const float* __restrict__ v, const float* __restrict__ c,
                      __nv_bfloat16* __restrict__ d) {
    int i = blockIdx.x * blockDim.x + threadIdx.x;
    if (i >= NTOT * 64) return;
    const float* src = (i < NVAR * 64) ? v : c - (size_t)NVAR * 256;
    float4 t = ((const float4*)src)[i];
    __nv_bfloat162 lo = __float22bfloat162_rn(make_float2(t.x, t.y));
    __nv_bfloat162 hi = __float22bfloat162_rn(make_float2(t.z, t.w));
    ((uint2*)d)[i] = make_uint2(*(uint32_t*)&lo, *(uint32_t*)&hi);
}
__global__ void setup_misc(const float* __restrict__ Wq, const float* __restrict__ Wkv,
                           const float* __restrict__ bq, const float* __restrict__ bkv,
                           const float* __restrict__ w1, const float* __restrict__ w2,
                           const float* __restrict__ w3, const float* __restrict__ w4,
                           __nv_bfloat16* __restrict__ wqkvb,
                           __nv_bfloat16* __restrict__ ffnw,
                           float* __restrict__ b768) {
    int blk = blockIdx.x;
    int tid = threadIdx.x;
    if (blk < 256) {
        int i = blk * 256 + tid;
        int which = i >> 14;
        int j = i & 16383;
        const float* src = (which == 0) ? w1 : (which == 1) ? w2 : (which == 2) ? w3 : w4;
        float4 t = ((const float4*)src)[j];
        __nv_bfloat162 lo = __float22bfloat162_rn(make_float2(t.x, t.y));
        __nv_bfloat162 hi = __float22bfloat162_rn(make_float2(t.z, t.w));
        ((uint2*)(ffnw + (size_t)which * 65536))[j] =
            make_uint2(*(uint32_t*)&lo, *(uint32_t*)&hi);
    } else if (blk < 1024) {
        int i = (blk - 256) * 256 + tid;
        int k = i / 768, j = i % 768;
        float val = (j < 256) ? Wq[k * 256 + j] : Wkv[k * 512 + (j - 256)];
        wqkvb[i] = __float2bfloat16(val);
    } else {
        int j = (blk - 1024) * 256 + tid;
        if (j < 768) b768[j] = (j < 256) ? bq[j] : bkv[j - 256];
    }
}

// ---------------- CSR build ----------------
// lists: L0 v-pos [0,NVAR), L1 v-neg [NVAR,2NVAR), L2 c-pos, L3 c-neg
__global__ void count_deg(const int* __restrict__ adj_pos, const int* __restrict__ adj_neg,
                          int E, int* __restrict__ deg) {
    int i = blockIdx.x * blockDim.x + threadIdx.x;
    if (i >= 2 * E) return;
    int pol = i >= E;
    int e = i - (pol ? E : 0);
    const int* adj = pol ? adj_neg : adj_pos;
    int cn = adj[e], vn = adj[E + e];
    atomicAdd(&deg[(pol ? NVAR : 0) + vn], 1);
    atomicAdd(&deg[2 * NVAR + (pol ? NCLS : 0) + cn], 1);
}

__global__ void scan_blk(const int* __restrict__ deg, int* __restrict__ excl,
                         int* __restrict__ bsum, int n) {
    __shared__ int ws[32];
    int idx = blockIdx.x * 1024 + threadIdx.x;
    int lane = threadIdx.x & 31;
    int warp = threadIdx.x >> 5;
    int orig = (idx < n) ? deg[idx] : 0;
    int val = orig;
    #pragma unroll
    for (int off = 1; off < 32; off <<= 1) {
        int t = __shfl_up_sync(0xffffffffu, val, off);
        if (lane >= off) val += t;
    }
    if (lane == 31) ws[warp] = val;
    __syncthreads();
    if (warp == 0) {
        int w = ws[lane];
        #pragma unroll
        for (int off = 1; off < 32; off <<= 1) {
            int t = __shfl_up_sync(0xffffffffu, w, off);
            if (lane >= off) w += t;
        }
        ws[lane] = w;
    }
    __syncthreads();
    int incl = val + (warp > 0 ? ws[warp - 1] : 0);
    if (idx < n) excl[idx] = incl - orig;
    if (threadIdx.x == 1023) bsum[blockIdx.x] = incl;
}

__global__ void scan_top(int* __restrict__ bsum, int nb) {
    __shared__ int sh[256];
    int tid = threadIdx.x;
    sh[tid] = (tid < nb) ? bsum[tid] : 0;
    __syncthreads();
    if (tid == 0) {
        int run = 0;
        for (int i = 0; i < nb; i++) { int t = sh[i]; sh[i] = run; run += t; }
    }
    __syncthreads();
    if (tid < nb) bsum[tid] = sh[tid];
}

__global__ void add_off(int* __restrict__ excl, int* __restrict__ cur,
                        const int* __restrict__ bsum, int n) {
    int idx = blockIdx.x * 1024 + threadIdx.x;
    if (idx >= n) return;
    int v = excl[idx] + bsum[blockIdx.x];
    excl[idx] = v;
    cur[idx] = v;
}

__global__ void fill_slots(const int* __restrict__ adj_pos, const int* __restrict__ adj_neg,
                           int E, int* __restrict__ cur, int* __restrict__ slots) {
    int i = blockIdx.x * blockDim.x + threadIdx.x;
    if (i >= 2 * E) return;
    int pol = i >= E;
    int e = i - (pol ? E : 0);
    const int* adj = pol ? adj_neg : adj_pos;
    int cn = adj[e], vn = adj[E + e];
    int s1 = atomicAdd(&cur[(pol ? NVAR : 0) + vn], 1);
    slots[s1] = cn;
    int s2 = atomicAdd(&cur[2 * NVAR + (pol ? NCLS : 0) + cn], 1);
    slots[s2] = vn;
}

// ---------------- gather attention: one warp per node, both polarities ----------------
// lane owns dims [lane*8, lane*8+8); head = lane>>2.
__global__ void gather_attn(
    const __nv_bfloat16* __restrict__ Qb,
    const __nv_bfloat16* __restrict__ KVb,
    const float* __restrict__ Vf,
    const int* __restrict__ excl, const int* __restrict__ cur,
    const int* __restrict__ slots,
    int base0, int base1,
    float* __restrict__ out, int nNodes)
{
    int gw = blockIdx.x * (blockDim.x >> 5) + (threadIdx.x >> 5);
    int lane = threadIdx.x & 31;
    if (gw >= nNodes) return;

    float qf[8];
    {
        uint4 qu = *(const uint4*)&Qb[(size_t)gw * 512 + lane * 8];
        const __nv_bfloat162* qp = (const __nv_bfloat162*)&qu;
        #pragma unroll
        for (int i = 0; i < 4; i++) {
            float2 f = __bfloat1622float2(qp[i]);
            qf[i * 2] = f.x; qf[i * 2 + 1] = f.y;
        }
    }

    float res[8];
    #pragma unroll
    for (int i = 0; i < 8; i++) res[i] = 0.0f;

    #pragma unroll
    for (int L = 0; L < 2; L++) {
        int li = (L ? base1 : base0) + gw;
        int j0 = excl[li], j1 = cur[li];
        float den = 0.0f;
        float acc[8];
        #pragma unroll
        for (int i = 0; i < 8; i++) acc[i] = 0.0f;
        for (int j = j0; j < j1; j++) {
            int src = slots[j];
            uint4 ku = *(const uint4*)&KVb[(size_t)src * 512 + 256 + lane * 8];
            const __nv_bfloat162* kp = (const __nv_bfloat162*)&ku;
            float p = 0.0f;
            #pragma unroll
            for (int i = 0; i < 4; i++) {
                float2 f = __bfloat1622float2(kp[i]);
                p += qf[i * 2] * f.x + qf[i * 2 + 1] * f.y;
            }
            p += __shfl_xor_sync(0xffffffffu, p, 1);
            p += __shfl_xor_sync(0xffffffffu, p, 2);
            float e = __expf(p * 0.17677669529663687f);
            den += e;
            const float4* v4 = (const float4*)&Vf[(size_t)src * 256 + lane * 8];
            float4 a = v4[0], b = v4[1];
            acc[0] += e * a.x; acc[1] += e * a.y; acc[2] += e * a.z; acc[3] += e * a.w;
            acc[4] += e * b.x; acc[5] += e * b.y; acc[6] += e * b.z; acc[7] += e * b.w;
        }
        if (den > 0.0f) {
            #pragma unroll
            for (int i = 0; i < 8; i++) res[i] += acc[i] / den;
        }
    }

    float4 o0 = make_float4(res[0], res[1], res[2], res[3]);
    float4 o1 = make_float4(res[4], res[5], res[6], res[7]);
    *(float4*)&out[(size_t)gw * 256 + lane * 8] = o0;
    *(float4*)&out[(size_t)gw * 256 + lane * 8 + 4] = o1;
}

// ---------------- bf16 tensor-core GEMM (unchanged from R14) ----------------
#define BM 128
#define BN 128
#define BK 32
#define ASTR 40
#define BSTR 136

__global__ __launch_bounds__(256, 2) void tgemm(
    const __nv_bfloat16* __restrict__ A, int lda,
    const __nv_bfloat16* __restrict__ W1, const __nv_bfloat16* __restrict__ W2, int nsplit,
    const float* __restrict__ bias1, const float* __restrict__ bias2,
    float* __restrict__ C, int cfrom, int cs,
    __nv_bfloat16* __restrict__ Cb, int cbto, int cbs,
    int N, int M, int gelu)
{
    __shared__ __nv_bfloat16 As[2][BM * ASTR];
    __shared__ __nv_bfloat16 Ws[2][BK * BSTR];

    int tid = threadIdx.x;
    int lane = tid & 31;
    int warp = tid >> 5;
    int wm = (warp & 3) * 32;
    int wn = (warp >> 2) * 64;
    int bm = blockIdx.y * BM;
    int bn = blockIdx.x * BN;

    bool second = (W2 != nullptr) && (bm >= nsplit);
    const __nv_bfloat16* W = second ? W2 : W1;
    const float* bias = second ? bias2 : bias1;

    uint32_t as_base = (uint32_t)__cvta_generic_to_shared(&As[0][0]);
    uint32_t ws_base = (uint32_t)__cvta_generic_to_shared(&Ws[0][0]);
    const uint32_t as_sz = BM * ASTR * 2;
    const uint32_t ws_sz = BK * BSTR * 2;

    int a_row[2], a_col[2], w_row[2], w_col[2];
    uint32_t a_dst[2], w_dst[2];
    #pragma unroll
    for (int i = 0; i < 2; i++) {
        int g = tid + i * 256;
        a_row[i] = (tid * 2 + i) >> 2;
        a_col[i] = ((tid * 2 + i) & 3) * 8;
        w_row[i] = g >> 4;
        w_col[i] = (g & 15) * 8;
        a_dst[i] = as_base + (uint32_t)(a_row[i] * ASTR + a_col[i]) * 2;
        w_dst[i] = ws_base + (uint32_t)(w_row[i] * BSTR + w_col[i]) * 2;
    }

    float acc[2][8][4];
    #pragma unroll
    for (int mt = 0; mt < 2; mt++)
        #pragma unroll
        for (int nt = 0; nt < 8; nt++)
            #pragma unroll
            for (int i = 0; i < 4; i++) acc[mt][nt][i] = 0.0f;

    int a_r = lane & 15;
    int a_c = (lane >> 4) * 8;

    #pragma unroll
    for (int i = 0; i < 2; i++) {
        int gr = bm + a_row[i];
        cp_async16(a_dst[i], &A[(size_t)gr * lda + a_col[i]], (gr < N) ? 16 : 0);
        cp_async16(w_dst[i], &W[(size_t)w_row[i] * M + bn + w_col[i]], 16);
    }
    CP_COMMIT();
    CP_WAIT0();
    __syncthreads();

    for (int s = 0; s < 8; s++) {
        int cur_ = s & 1, nxt = cur_ ^ 1;
        if (s < 7) {
            int k0 = (s + 1) * BK;
            #pragma unroll
            for (int i = 0; i < 2; i++) {
                int gr = bm + a_row[i];
                cp_async16(a_dst[i] + nxt * as_sz,
                           &A[(size_t)gr * lda + k0 + a_col[i]], (gr < N) ? 16 : 0);
                cp_async16(w_dst[i] + nxt * ws_sz,
                           &W[(size_t)(k0 + w_row[i]) * M + bn + w_col[i]], 16);
            }
            CP_COMMIT();
        }

        uint32_t asb = as_base + cur_ * as_sz;
        uint32_t wsb = ws_base + cur_ * ws_sz;
        #pragma unroll
        for (int ks = 0; ks < 2; ks++) {
            int kb = ks * 16;
            uint32_t af[2][4], bf[4][4];
            #pragma unroll
            for (int mt = 0; mt < 2; mt++) {
                int row = wm + mt * 16 + a_r;
                int col = kb + a_c;
                ldsm_x4(af[mt], asb + (uint32_t)(row * ASTR + col) * 2);
            }
            #pragma unroll
            for (int p = 0; p < 4; p++) {
                int row = kb + (lane & 15);
                int col = wn + p * 16 + (lane >> 4) * 8;
                ldsm_x4_trans(bf[p], wsb + (uint32_t)(row * BSTR + col) * 2);
            }
            #pragma unroll
            for (int mt = 0; mt < 2; mt++)
                #pragma unroll
                for (int nt = 0; nt < 8; nt++)
                    mma_bf16(acc[mt][nt], af[mt], &bf[nt >> 1][(nt & 1) * 2]);
        }

        if (s < 7) {
            CP_WAIT0();
            __syncthreads();
        }
    }

    #pragma unroll
    for (int mt = 0; mt < 2; mt++) {
        int r0 = bm + wm + mt * 16 + (lane >> 2);
        #pragma unroll
        for (int nt = 0; nt < 8; nt++) {
            int cb = bn + wn + nt * 8 + (lane & 3) * 2;
            float b0 = bias[cb], b1 = bias[cb + 1];
            float2 lo = make_float2(acc[mt][nt][0] + b0, acc[mt][nt][1] + b1);
            float2 hi = make_float2(acc[mt][nt][2] + b0, acc[mt][nt][3] + b1);
            if (gelu) {
                lo.x = 0.5f * lo.x * (1.0f + erff(lo.x * 0.70710678118654752f));
                lo.y = 0.5f * lo.y * (1.0f + erff(lo.y * 0.70710678118654752f));
                hi.x = 0.5f * hi.x * (1.0f + erff(hi.x * 0.70710678118654752f));
                hi.y = 0.5f * hi.y * (1.0f + erff(hi.y * 0.70710678118654752f));
            }
            if (C && cb >= cfrom) {
                if (r0 < N)     *(float2*)&C[(size_t)r0 * cs + cb - cfrom] = lo;
                if (r0 + 8 < N) *(float2*)&C[(size_t)(r0 + 8) * cs + cb - cfrom] = hi;
            }
            if (Cb && cb < cbto) {
                __nv_bfloat162 blo = __float22bfloat162_rn(lo);
                __nv_bfloat162 bhi = __float22bfloat162_rn(hi);
                if (r0 < N)     *(__nv_bfloat162*)&Cb[(size_t)r0 * cbs + cb] = blo;
                if (r0 + 8 < N) *(__nv_bfloat162*)&Cb[(size_t)(r0 + 8) * cbs + cb] = bhi;
            }
        }
    }
}

// ---------------- merged attention LN: y = LN(x + att) ----------------
__global__ void ln_att_m(const float* __restrict__ xv, const float* __restrict__ xc,
                         const float* __restrict__ att,
                         const float* __restrict__ gv, const float* __restrict__ bv,
                         const float* __restrict__ gc, const float* __restrict__ bc,
                         float* __restrict__ y, __nv_bfloat16* __restrict__ yb)
{
    int gr = blockIdx.x * (blockDim.x >> 5) + (threadIdx.x >> 5);
    int lane = threadIdx.x & 31;
    if (gr >= NTOT) return;
    bool isv = gr < NVAR;
    int node = isv ? gr : gr - NVAR;
    const float* x = isv ? xv : xc;
    const float* g = isv ? gv : gc;
    const float* b = isv ? bv : bc;
    size_t orow = isv ? (size_t)gr : (size_t)NVP + node;

    float vals[8];
    float s = 0.0f;
    #pragma unroll
    for (int i = 0; i < 8; i++) {
        size_t xidx = (size_t)node * 256 + i * 32 + lane;
        float a = x[xidx] + att[(size_t)gr * 256 + i * 32 + lane];
        vals[i] = a;
        s += a;
    }
    #pragma unroll
    for (int o = 16; o > 0; o >>= 1) s += __shfl_xor_sync(0xffffffffu, s, o);
    float mean = s * (1.0f / 256.0f);
    float v2 = 0.0f;
    #pragma unroll
    for (int i = 0; i < 8; i++) { float d = vals[i] - mean; v2 += d * d; }
    #pragma unroll
    for (int o = 16; o > 0; o >>= 1) v2 += __shfl_xor_sync(0xffffffffu, v2, o);
    float rstd = rsqrtf(v2 * (1.0f / 256.0f) + 1e-5f);
    #pragma unroll
    for (int i = 0; i < 8; i++) {
        int cidx = i * 32 + lane;
        float out = (vals[i] - mean) * rstd * g[cidx] + b[cidx];
        y[orow * 256 + cidx] = out;
        yb[orow * 256 + cidx] = __float2bfloat16(out);
    }
}

// ---------------- merged final LN: y = LN(x + a_bf16) ----------------
__global__ void ln_add_m(const float* __restrict__ x, const __nv_bfloat16* __restrict__ a,
                         const float* __restrict__ gv, const float* __restrict__ bv,
                         const float* __restrict__ gc, const float* __restrict__ bc,
                         float* __restrict__ out_v, float* __restrict__ out_c)
{
    int gr = blockIdx.x * (blockDim.x >> 5) + (threadIdx.x >> 5);
    int lane = threadIdx.x & 31;
    if (gr >= NTOT) return;
    bool isv = gr < NVAR;
    int node = isv ? gr : gr - NVAR;
    size_t brow = isv ? (size_t)gr : (size_t)NVP + node;
    const float* g = isv ? gv : gc;
    const float* b = isv ? bv : bc;
    float* y = isv ? out_v : out_c;

    float vals[8];
    float s = 0.0f;
    #pragma unroll
    for (int i = 0; i < 8; i++) {
        size_t idx = brow * 256 + i * 32 + lane;
        vals[i] = x[idx] + __bfloat162float(a[idx]);
        s += vals[i];
    }
    #pragma unroll
    for (int o = 16; o > 0; o >>= 1) s += __shfl_xor_sync(0xffffffffu, s, o);
    float mean = s * (1.0f / 256.0f);
    float v2 = 0.0f;
    #pragma unroll
    for (int i = 0; i < 8; i++) { float d = vals[i] - mean; v2 += d * d; }
    #pragma unroll
    for (int o = 16; o > 0; o >>= 1) v2 += __shfl_xor_sync(0xffffffffu, v2, o);
    float rstd = rsqrtf(v2 * (1.0f / 256.0f) + 1e-5f);
    #pragma unroll
    for (int i = 0; i < 8; i++) {
        int cidx = i * 32 + lane;
        y[(size_t)node * 256 + cidx] = (vals[i] - mean) * rstd * g[cidx] + b[cidx];
    }
}

extern "C" void kernel_launch(void* const* d_in, const int* in_sizes, int n_in,
                              void* d_out, int out_size)
{
    const float* v       = (const float*)d_in[0];
    const float* c       = (const float*)d_in[1];
    const int*   adj_pos = (const int*)d_in[2];
    const int*   adj_neg = (const int*)d_in[3];
    const float* Wq      = (const float*)d_in[4];
    const float* bq      = (const float*)d_in[5];
    const float* Wkv     = (const float*)d_in[6];
    const float* bkv     = (const float*)d_in[7];
    const float* fvw1    = (const float*)d_in[8];
    const float* fvb1    = (const float*)d_in[9];
    const float* fvw2    = (const float*)d_in[10];
    const float* fvb2    = (const float*)d_in[11];
    const float* fcw1    = (const float*)d_in[12];
    const float* fcb1    = (const float*)d_in[13];
    const float* fcw2    = (const float*)d_in[14];
    const float* fcb2    = (const float*)d_in[15];
    const float* lavg    = (const float*)d_in[16];
    const float* lavb    = (const float*)d_in[17];
    const float* lfvg    = (const float*)d_in[18];
    const float* lfvb    = (const float*)d_in[19];
    const float* lacg    = (const float*)d_in[20];
    const float* lacb    = (const float*)d_in[21];
    const float* lfcg    = (const float*)d_in[22];
    const float* lfcb    = (const float*)d_in[23];

    int E = in_sizes[2] / 2;

    float* buf;
    cudaGetSymbolAddress((void**)&buf, g_scratch);

    float* att  = buf + OFF_ATT;
    float* v1m  = buf + OFF_V1M;
    float* b768 = buf + OFF_B768;
    float* pvf  = buf + OFF_PVF;

    int* iarr  = (int*)(buf + OFF_IDX);
    int* deg   = iarr + IDX_DEG;
    int* excl  = iarr + IDX_EXCL;
    int* curp  = iarr + IDX_CUR;
    int* bsum  = iarr + IDX_BSUM;
    int* slots = iarr + IDX_SLOTS;

    __nv_bfloat16* bfb   = (__nv_bfloat16*)(buf + OFF_BF);
    __nv_bfloat16* xb    = bfb + B_XB;
    __nv_bfloat16* pb    = bfb + B_PB;
    __nv_bfloat16* x1b   = bfb + B_X1B;
    __nv_bfloat16* hidb  = bfb + B_HID;
    __nv_bfloat16* tmpb  = bfb + B_TMPB;
    __nv_bfloat16* wqkvb = bfb + B_WQKV;
    __nv_bfloat16* ffnw  = bfb + B_FFNW;
    __nv_bfloat16* fvw1b = ffnw;
    __nv_bfloat16* fvw2b = ffnw + 65536;
    __nv_bfloat16* fcw1b = ffnw + 131072;
    __nv_bfloat16* fcw2b = ffnw + 196608;

    __nv_bfloat16* pvb = pb;
    __nv_bfloat16* pcb = pb + (size_t)NVAR * 512;
    float* vfv = pvf;
    float* vfc = pvf + (size_t)NVAR * 256;

    float* out_v = (float*)d_out;
    float* out_c = out_v + (size_t)NVAR * DIM;

    // ---- setup + CSR build ----
    cvt_x<<<(NTOT * 64 + 255) / 256, 256>>>(v, c, xb);
    setup_misc<<<1027, 256>>>(Wq, Wkv, bq, bkv, fvw1, fvw2, fcw1, fcw2,
                              wqkvb, ffnw, b768);
    cudaMemsetAsync(deg, 0, NSEG * sizeof(int), 0);
    count_deg<<<(2 * E + 255) / 256, 256>>>(adj_pos, adj_neg, E, deg);
    int nblk = (NSEG + 1023) / 1024;   // 176
    scan_blk<<<nblk, 1024>>>(deg, excl, bsum, NSEG);
    scan_top<<<1, 256>>>(bsum, nblk);
    add_off<<<nblk, 1024>>>(excl, curp, bsum, NSEG);
    fill_slots<<<(2 * E + 255) / 256, 256>>>(adj_pos, adj_neg, E, curp, slots);

    // ---- merged projection: 90000 x 768, bf16 [q|k] + compact fp32 v ----
    {
        dim3 grid(768 / BN, (NTOT + BM - 1) / BM);
        tgemm<<<grid, 256>>>(xb, 256, wqkvb, nullptr, 0, b768, b768,
                             pvf, 512, 256, pb, 512, 512, NTOT, 768, 0);
    }

    // ---- gather attention: one warp per node, per side ----
    gather_attn<<<(NVAR + 7) / 8, 256>>>(pvb, pcb, vfc, excl, curp, slots,
                                         0, NVAR, att, NVAR);
    gather_attn<<<(NCLS + 7) / 8, 256>>>(pcb, pvb, vfv, excl, curp, slots,
                                         2 * NVAR, 2 * NVAR + NCLS,
                                         att + (size_t)NVAR * 256, NCLS);

    // ---- merged attention LN ----
    ln_att_m<<<(NTOT + 7) / 8, 256>>>(v, c, att, lavg, lavb, lacg, lacb, v1m, x1b);

    // ---- merged FFN; FFN2 out bf16 ----
    {
        dim3 grid(256 / BN, (NTOTP + BM - 1) / BM);
        tgemm<<<grid, 256>>>(x1b, 256, fvw1b, fcw1b, NVP, fvb1, fcb1,
                             nullptr, 1 << 30, 0, hidb, 256, 256, NTOTP, 256, 1);
        tgemm<<<grid, 256>>>(hidb, 256, fvw2b, fcw2b, NVP, fvb2, fcb2,
                             nullptr, 1 << 30, 0, tmpb, 256, 256, NTOTP, 256, 0);
    }

    // ---- merged final LN ----
    ln_add_m<<<(NTOT + 7) / 8, 256>>>(v1m, tmpb, lfvg, lfvb, lfcg, lfcb, out_v, out_c);
}

// round 16
// speedup vs baseline: 1.3704x; 1.0480x over previous
#include <cuda_runtime.h>
#include <cuda_bf16.h>
#include <math.h>
#include <stdint.h>

#define NVAR 30000
#define NCLS 60000
#define NTOT 90000
#define NVP  30080
#define NTOTP 90080
#define DIM 256
#define NHEAD 8
#define NSEG (2 * NVAR + 2 * NCLS)     // 180000 CSR segments

// ---------------- scratch layout (float units) ----------------
#define OFF_ATT    0ull             // 90000*256 fp32
#define OFF_V1M    23040000ull      // 90080*256 fp32
#define OFF_B768   46100480ull      // 1024
#define OFF_IDX    46101504ull      // int area
#define IDX_DEG    0
#define IDX_EXCL   180000
#define IDX_CUR    360000
#define IDX_BSUM   540000           // 256
#define IDX_SLOTS  540256           // 480000
#define OFF_BF     47121760ull      // bf16 area (bf16-element offsets)
#define B_XB    0ull                // 90000*256
#define B_PB    23040000ull         // 90000*768 packed [q|k|v] bf16
#define B_X1B   92160000ull         // 90080*256
#define B_HID   115220480ull
#define B_TMPB  138280960ull
#define B_WQKV  161341440ull        // 256*768
#define B_FFNW  161538048ull        // 4*65536
// bf16 total 161,800,192 -> 80,900,096 floats
#define SCRATCH_TOTAL 128021856ull

__device__ float g_scratch[SCRATCH_TOTAL];

// ---------------- helpers ----------------
__device__ __forceinline__ void ldsm_x4(uint32_t* r, uint32_t saddr) {
    asm volatile("ldmatrix.sync.aligned.m8n8.x4.shared.b16 {%0,%1,%2,%3}, [%4];"
                 : "=r"(r[0]), "=r"(r[1]), "=r"(r[2]), "=r"(r[3]) : "r"(saddr));
}
__device__ __forceinline__ void ldsm_x4_trans(uint32_t* r, uint32_t saddr) {
    asm volatile("ldmatrix.sync.aligned.m8n8.x4.trans.shared.b16 {%0,%1,%2,%3}, [%4];"
                 : "=r"(r[0]), "=r"(r[1]), "=r"(r[2]), "=r"(r[3]) : "r"(saddr));
}
__device__ __forceinline__ void mma_bf16(float* d, const uint32_t* a, const uint32_t* b) {
    asm volatile(
        "mma.sync.aligned.m16n8k16.row.col.f32.bf16.bf16.f32 "
        "{%0,%1,%2,%3}, {%4,%5,%6,%7}, {%8,%9}, {%0,%1,%2,%3};"
        : "+f"(d[0]), "+f"(d[1]), "+f"(d[2]), "+f"(d[3])
        : "r"(a[0]), "r"(a[1]), "r"(a[2]), "r"(a[3]),
          "r"(b[0]), "r"(b[1]));
}
__device__ __forceinline__ void cp_async16(uint32_t saddr, const void* gaddr, int src_size) {
    asm volatile("cp.async.cg.shared.global [%0], [%1], 16, %2;"
                 :: "r"(saddr), "l"(gaddr), "r"(src_size));
}
#define CP_COMMIT() asm volatile("cp.async.commit_group;" ::: "memory")
#define CP_WAIT0()  asm volatile("cp.async.wait_group 0;" ::: "memory")

// ---------------- conversion / setup kernels ----------------
__global__ void cvt_x(const float* __restrict__ v, const float* __restrict__ c,
                      __nv_bfloat16* __restrict__ d) {
    int i = blockIdx.x * blockDim.x + threadIdx.x;
    if (i >= NTOT * 64) return;
    const float* src = (i < NVAR * 64) ? v : c - (size_t)NVAR * 256;
    float4 t = ((const float4*)src)[i];
    __nv_bfloat162 lo = __float22bfloat162_rn(make_float2(t.x, t.y));
    __nv_bfloat162 hi = __float22bfloat162_rn(make_float2(t.z, t.w));
    ((uint2*)d)[i] = make_uint2(*(uint32_t*)&lo, *(uint32_t*)&hi);
}
__global__ void setup_misc(const float* __restrict__ Wq, const float* __restrict__ Wkv,
                           const float* __restrict__ bq, const float* __restrict__ bkv,
                           const float* __restrict__ w1, const float* __restrict__ w2,
                           const float* __restrict__ w3, const float* __restrict__ w4,
                           __nv_bfloat16* __restrict__ wqkvb,
                           __nv_bfloat16* __restrict__ ffnw,
                           float* __restrict__ b768) {
    int blk = blockIdx.x;
    int tid = threadIdx.x;
    if (blk < 256) {
        int i = blk * 256 + tid;
        int which = i >> 14;
        int j = i & 16383;
        const float* src = (which == 0) ? w1 : (which == 1) ? w2 : (which == 2) ? w3 : w4;
        float4 t = ((const float4*)src)[j];
        __nv_bfloat162 lo = __float22bfloat162_rn(make_float2(t.x, t.y));
        __nv_bfloat162 hi = __float22bfloat162_rn(make_float2(t.z, t.w));
        ((uint2*)(ffnw + (size_t)which * 65536))[j] =
            make_uint2(*(uint32_t*)&lo, *(uint32_t*)&hi);
    } else if (blk < 1024) {
        int i = (blk - 256) * 256 + tid;
        int k = i / 768, j = i % 768;
        float val = (j < 256) ? Wq[k * 256 + j] : Wkv[k * 512 + (j - 256)];
        wqkvb[i] = __float2bfloat16(val);
    } else {
        int j = (blk - 1024) * 256 + tid;
        if (j < 768) b768[j] = (j < 256) ? bq[j] : bkv[j - 256];
    }
}

// ---------------- CSR build ----------------
__global__ void count_deg(const int* __restrict__ adj_pos, const int* __restrict__ adj_neg,
                          int E, int* __restrict__ deg) {
    int i = blockIdx.x * blockDim.x + threadIdx.x;
    if (i >= 2 * E) return;
    int pol = i >= E;
    int e = i - (pol ? E : 0);
    const int* adj = pol ? adj_neg : adj_pos;
    int cn = adj[e], vn = adj[E + e];
    atomicAdd(&deg[(pol ? NVAR : 0) + vn], 1);
    atomicAdd(&deg[2 * NVAR + (pol ? NCLS : 0) + cn], 1);
}

__global__ void scan_blk(const int* __restrict__ deg, int* __restrict__ excl,
                         int* __restrict__ bsum, int n) {
    __shared__ int ws[32];
    int idx = blockIdx.x * 1024 + threadIdx.x;
    int lane = threadIdx.x & 31;
    int warp = threadIdx.x >> 5;
    int orig = (idx < n) ? deg[idx] : 0;
    int val = orig;
    #pragma unroll
    for (int off = 1; off < 32; off <<= 1) {
        int t = __shfl_up_sync(0xffffffffu, val, off);
        if (lane >= off) val += t;
    }
    if (lane == 31) ws[warp] = val;
    __syncthreads();
    if (warp == 0) {
        int w = ws[lane];
        #pragma unroll
        for (int off = 1; off < 32; off <<= 1) {
            int t = __shfl_up_sync(0xffffffffu, w, off);
            if (lane >= off) w += t;
        }
        ws[lane] = w;
    }
    __syncthreads();
    int incl = val + (warp > 0 ? ws[warp - 1] : 0);
    if (idx < n) excl[idx] = incl - orig;
    if (threadIdx.x == 1023) bsum[blockIdx.x] = incl;
}

__global__ void scan_top(int* __restrict__ bsum, int nb) {
    __shared__ int sh[256];
    int tid = threadIdx.x;
    sh[tid] = (tid < nb) ? bsum[tid] : 0;
    __syncthreads();
    if (tid == 0) {
        int run = 0;
        for (int i = 0; i < nb; i++) { int t = sh[i]; sh[i] = run; run += t; }
    }
    __syncthreads();
    if (tid < nb) bsum[tid] = sh[tid];
}

__global__ void add_off(int* __restrict__ excl, int* __restrict__ cur,
                        const int* __restrict__ bsum, int n) {
    int idx = blockIdx.x * 1024 + threadIdx.x;
    if (idx >= n) return;
    int v = excl[idx] + bsum[blockIdx.x];
    excl[idx] = v;
    cur[idx] = v;
}

__global__ void fill_slots(const int* __restrict__ adj_pos, const int* __restrict__ adj_neg,
                           int E, int* __restrict__ cur, int* __restrict__ slots) {
    int i = blockIdx.x * blockDim.x + threadIdx.x;
    if (i >= 2 * E) return;
    int pol = i >= E;
    int e = i - (pol ? E : 0);
    const int* adj = pol ? adj_neg : adj_pos;
    int cn = adj[e], vn = adj[E + e];
    int s1 = atomicAdd(&cur[(pol ? NVAR : 0) + vn], 1);
    slots[s1] = cn;
    int s2 = atomicAdd(&cur[2 * NVAR + (pol ? NCLS : 0) + cn], 1);
    slots[s2] = vn;
}

// ---------------- gather attention: one warp per node, both polarities ----------------
// Packed rows stride 768: q at +0, k at +256, v at +512. lane owns dims [lane*8,+8).
__global__ void gather_attn(
    const __nv_bfloat16* __restrict__ Qb,
    const __nv_bfloat16* __restrict__ KVb,
    const int* __restrict__ excl, const int* __restrict__ cur,
    const int* __restrict__ slots,
    int base0, int base1,
    float* __restrict__ out, int nNodes)
{
    int gw = blockIdx.x * (blockDim.x >> 5) + (threadIdx.x >> 5);
    int lane = threadIdx.x & 31;
    if (gw >= nNodes) return;

    float qf[8];
    {
        uint4 qu = *(const uint4*)&Qb[(size_t)gw * 768 + lane * 8];
        const __nv_bfloat162* qp = (const __nv_bfloat162*)&qu;
        #pragma unroll
        for (int i = 0; i < 4; i++) {
            float2 f = __bfloat1622float2(qp[i]);
            qf[i * 2] = f.x; qf[i * 2 + 1] = f.y;
        }
    }

    float res[8];
    #pragma unroll
    for (int i = 0; i < 8; i++) res[i] = 0.0f;

    #pragma unroll
    for (int L = 0; L < 2; L++) {
        int li = (L ? base1 : base0) + gw;
        int j0 = excl[li], j1 = cur[li];
        float den = 0.0f;
        float acc[8];
        #pragma unroll
        for (int i = 0; i < 8; i++) acc[i] = 0.0f;
        for (int j = j0; j < j1; j++) {
            int src = slots[j];
            const __nv_bfloat16* row = &KVb[(size_t)src * 768];
            uint4 ku = *(const uint4*)&row[256 + lane * 8];
            const __nv_bfloat162* kp = (const __nv_bfloat162*)&ku;
            float p = 0.0f;
            #pragma unroll
            for (int i = 0; i < 4; i++) {
                float2 f = __bfloat1622float2(kp[i]);
                p += qf[i * 2] * f.x + qf[i * 2 + 1] * f.y;
            }
            p += __shfl_xor_sync(0xffffffffu, p, 1);
            p += __shfl_xor_sync(0xffffffffu, p, 2);
            float e = __expf(p * 0.17677669529663687f);
            den += e;
            uint4 vu = *(const uint4*)&row[512 + lane * 8];
            const __nv_bfloat162* vp = (const __nv_bfloat162*)&vu;
            #pragma unroll
            for (int i = 0; i < 4; i++) {
                float2 f = __bfloat1622float2(vp[i]);
                acc[i * 2]     += e * f.x;
                acc[i * 2 + 1] += e * f.y;
            }
        }
        if (den > 0.0f) {
            #pragma unroll
            for (int i = 0; i < 8; i++) res[i] += acc[i] / den;
        }
    }

    *(float4*)&out[(size_t)gw * 256 + lane * 8] =
        make_float4(res[0], res[1], res[2], res[3]);
    *(float4*)&out[(size_t)gw * 256 + lane * 8 + 4] =
        make_float4(res[4], res[5], res[6], res[7]);
}

// ---------------- bf16 tensor-core GEMM ----------------
#define BM 128
#define BN 128
#define BK 32
#define ASTR 40
#define BSTR 136

__global__ __launch_bounds__(256, 2) void tgemm(
    const __nv_bfloat16* __restrict__ A, int lda,
    const __nv_bfloat16* __restrict__ W1, const __nv_bfloat16* __restrict__ W2, int nsplit,
    const float* __restrict__ bias1, const float* __restrict__ bias2,
    float* __restrict__ C, int cfrom, int cs,
    __nv_bfloat16* __restrict__ Cb, int cbto, int cbs,
    int N, int M, int gelu)
{
    __shared__ __nv_bfloat16 As[2][BM * ASTR];
    __shared__ __nv_bfloat16 Ws[2][BK * BSTR];

    int tid = threadIdx.x;
    int lane = tid & 31;
    int warp = tid >> 5;
    int wm = (warp & 3) * 32;
    int wn = (warp >> 2) * 64;
    int bm = blockIdx.y * BM;
    int bn = blockIdx.x * BN;

    bool second = (W2 != nullptr) && (bm >= nsplit);
    const __nv_bfloat16* W = second ? W2 : W1;
    const float* bias = second ? bias2 : bias1;

    uint32_t as_base = (uint32_t)__cvta_generic_to_shared(&As[0][0]);
    uint32_t ws_base = (uint32_t)__cvta_generic_to_shared(&Ws[0][0]);
    const uint32_t as_sz = BM * ASTR * 2;
    const uint32_t ws_sz = BK * BSTR * 2;

    int a_row[2], a_col[2], w_row[2], w_col[2];
    uint32_t a_dst[2], w_dst[2];
    #pragma unroll
    for (int i = 0; i < 2; i++) {
        int g = tid + i * 256;
        a_row[i] = (tid * 2 + i) >> 2;
        a_col[i] = ((tid * 2 + i) & 3) * 8;
        w_row[i] = g >> 4;
        w_col[i] = (g & 15) * 8;
        a_dst[i] = as_base + (uint32_t)(a_row[i] * ASTR + a_col[i]) * 2;
        w_dst[i] = ws_base + (uint32_t)(w_row[i] * BSTR + w_col[i]) * 2;
    }

    float acc[2][8][4];
    #pragma unroll
    for (int mt = 0; mt < 2; mt++)
        #pragma unroll
        for (int nt = 0; nt < 8; nt++)
            #pragma unroll
            for (int i = 0; i < 4; i++) acc[mt][nt][i] = 0.0f;

    int a_r = lane & 15;
    int a_c = (lane >> 4) * 8;

    #pragma unroll
    for (int i = 0; i < 2; i++) {
        int gr = bm + a_row[i];
        cp_async16(a_dst[i], &A[(size_t)gr * lda + a_col[i]], (gr < N) ? 16 : 0);
        cp_async16(w_dst[i], &W[(size_t)w_row[i] * M + bn + w_col[i]], 16);
    }
    CP_COMMIT();
    CP_WAIT0();
    __syncthreads();

    for (int s = 0; s < 8; s++) {
        int cur_ = s & 1, nxt = cur_ ^ 1;
        if (s < 7) {
            int k0 = (s + 1) * BK;
            #pragma unroll
            for (int i = 0; i < 2; i++) {
                int gr = bm + a_row[i];
                cp_async16(a_dst[i] + nxt * as_sz,
                           &A[(size_t)gr * lda + k0 + a_col[i]], (gr < N) ? 16 : 0);
                cp_async16(w_dst[i] + nxt * ws_sz,
                           &W[(size_t)(k0 + w_row[i]) * M + bn + w_col[i]], 16);
            }
            CP_COMMIT();
        }

        uint32_t asb = as_base + cur_ * as_sz;
        uint32_t wsb = ws_base + cur_ * ws_sz;
        #pragma unroll
        for (int ks = 0; ks < 2; ks++) {
            int kb = ks * 16;
            uint32_t af[2][4], bf[4][4];
            #pragma unroll
            for (int mt = 0; mt < 2; mt++) {
                int row = wm + mt * 16 + a_r;
                int col = kb + a_c;
                ldsm_x4(af[mt], asb + (uint32_t)(row * ASTR + col) * 2);
            }
            #pragma unroll
            for (int p = 0; p < 4; p++) {
                int row = kb + (lane & 15);
                int col = wn + p * 16 + (lane >> 4) * 8;
                ldsm_x4_trans(bf[p], wsb + (uint32_t)(row * BSTR + col) * 2);
            }
            #pragma unroll
            for (int mt = 0; mt < 2; mt++)
                #pragma unroll
                for (int nt = 0; nt < 8; nt++)
                    mma_bf16(acc[mt][nt], af[mt], &bf[nt >> 1][(nt & 1) * 2]);
        }

        if (s < 7) {
            CP_WAIT0();
            __syncthreads();
        }
    }

    #pragma unroll
    for (int mt = 0; mt < 2; mt++) {
        int r0 = bm + wm + mt * 16 + (lane >> 2);
        #pragma unroll
        for (int nt = 0; nt < 8; nt++) {
            int cb = bn + wn + nt * 8 + (lane & 3) * 2;
            float b0 = bias[cb], b1 = bias[cb + 1];
            float2 lo = make_float2(acc[mt][nt][0] + b0, acc[mt][nt][1] + b1);
            float2 hi = make_float2(acc[mt][nt][2] + b0, acc[mt][nt][3] + b1);
            if (gelu) {
                lo.x = 0.5f * lo.x * (1.0f + erff(lo.x * 0.70710678118654752f));
                lo.y = 0.5f * lo.y * (1.0f + erff(lo.y * 0.70710678118654752f));
                hi.x = 0.5f * hi.x * (1.0f + erff(hi.x * 0.70710678118654752f));
                hi.y = 0.5f * hi.y * (1.0f + erff(hi.y * 0.70710678118654752f));
            }
            if (C && cb >= cfrom) {
                if (r0 < N)     *(float2*)&C[(size_t)r0 * cs + cb - cfrom] = lo;
                if (r0 + 8 < N) *(float2*)&C[(size_t)(r0 + 8) * cs + cb - cfrom] = hi;
            }
            if (Cb && cb < cbto) {
                __nv_bfloat162 blo = __float22bfloat162_rn(lo);
                __nv_bfloat162 bhi = __float22bfloat162_rn(hi);
                if (r0 < N)     *(__nv_bfloat162*)&Cb[(size_t)r0 * cbs + cb] = blo;
                if (r0 + 8 < N) *(__nv_bfloat162*)&Cb[(size_t)(r0 + 8) * cbs + cb] = bhi;
            }
        }
    }
}

// ---------------- merged attention LN: y = LN(x + att) ----------------
__global__ void ln_att_m(const float* __restrict__ xv, const float* __restrict__ xc,
                         const float* __restrict__ att,
                         const float* __restrict__ gv, const float* __restrict__ bv,
                         const float* __restrict__ gc, const float* __restrict__ bc,
                         float* __restrict__ y, __nv_bfloat16* __restrict__ yb)
{
    int gr = blockIdx.x * (blockDim.x >> 5) + (threadIdx.x >> 5);
    int lane = threadIdx.x & 31;
    if (gr >= NTOT) return;
    bool isv = gr < NVAR;
    int node = isv ? gr : gr - NVAR;
    const float* x = isv ? xv : xc;
    const float* g = isv ? gv : gc;
    const float* b = isv ? bv : bc;
    size_t orow = isv ? (size_t)gr : (size_t)NVP + node;

    float vals[8];
    float s = 0.0f;
    #pragma unroll
    for (int i = 0; i < 8; i++) {
        size_t xidx = (size_t)node * 256 + i * 32 + lane;
        float a = x[xidx] + att[(size_t)gr * 256 + i * 32 + lane];
        vals[i] = a;
        s += a;
    }
    #pragma unroll
    for (int o = 16; o > 0; o >>= 1) s += __shfl_xor_sync(0xffffffffu, s, o);
    float mean = s * (1.0f / 256.0f);
    float v2 = 0.0f;
    #pragma unroll
    for (int i = 0; i < 8; i++) { float d = vals[i] - mean; v2 += d * d; }
    #pragma unroll
    for (int o = 16; o > 0; o >>= 1) v2 += __shfl_xor_sync(0xffffffffu, v2, o);
    float rstd = rsqrtf(v2 * (1.0f / 256.0f) + 1e-5f);
    #pragma unroll
    for (int i = 0; i < 8; i++) {
        int cidx = i * 32 + lane;
        float out = (vals[i] - mean) * rstd * g[cidx] + b[cidx];
        y[orow * 256 + cidx] = out;
        yb[orow * 256 + cidx] = __float2bfloat16(out);
    }
}

// ---------------- merged final LN: y = LN(x + a_bf16) ----------------
__global__ void ln_add_m(const float* __restrict__ x, const __nv_bfloat16* __restrict__ a,
                         const float* __restrict__ gv, const float* __restrict__ bv,
                         const float* __restrict__ gc, const float* __restrict__ bc,
                         float* __restrict__ out_v, float* __restrict__ out_c)
{
    int gr = blockIdx.x * (blockDim.x >> 5) + (threadIdx.x >> 5);
    int lane = threadIdx.x & 31;
    if (gr >= NTOT) return;
    bool isv = gr < NVAR;
    int node = isv ? gr : gr - NVAR;
    size_t brow = isv ? (size_t)gr : (size_t)NVP + node;
    const float* g = isv ? gv : gc;
    const float* b = isv ? bv : bc;
    float* y = isv ? out_v : out_c;

    float vals[8];
    float s = 0.0f;
    #pragma unroll
    for (int i = 0; i < 8; i++) {
        size_t idx = brow * 256 + i * 32 + lane;
        vals[i] = x[idx] + __bfloat162float(a[idx]);
        s += vals[i];
    }
    #pragma unroll
    for (int o = 16; o > 0; o >>= 1) s += __shfl_xor_sync(0xffffffffu, s, o);
    float mean = s * (1.0f / 256.0f);
    float v2 = 0.0f;
    #pragma unroll
    for (int i = 0; i < 8; i++) { float d = vals[i] - mean; v2 += d * d; }
    #pragma unroll
    for (int o = 16; o > 0; o >>= 1) v2 += __shfl_xor_sync(0xffffffffu, v2, o);
    float rstd = rsqrtf(v2 * (1.0f / 256.0f) + 1e-5f);
    #pragma unroll
    for (int i = 0; i < 8; i++) {
        int cidx = i * 32 + lane;
        y[(size_t)node * 256 + cidx] = (vals[i] - mean) * rstd * g[cidx] + b[cidx];
    }
}

extern "C" void kernel_launch(void* const* d_in, const int* in_sizes, int n_in,
                              void* d_out, int out_size)
{
    const float* v       = (const float*)d_in[0];
    const float* c       = (const float*)d_in[1];
    const int*   adj_pos = (const int*)d_in[2];
    const int*   adj_neg = (const int*)d_in[3];
    const float* Wq      = (const float*)d_in[4];
    const float* bq      = (const float*)d_in[5];
    const float* Wkv     = (const float*)d_in[6];
    const float* bkv     = (const float*)d_in[7];
    const float* fvw1    = (const float*)d_in[8];
    const float* fvb1    = (const float*)d_in[9];
    const float* fvw2    = (const float*)d_in[10];
    const float* fvb2    = (const float*)d_in[11];
    const float* fcw1    = (const float*)d_in[12];
    const float* fcb1    = (const float*)d_in[13];
    const float* fcw2    = (const float*)d_in[14];
    const float* fcb2    = (const float*)d_in[15];
    const float* lavg    = (const float*)d_in[16];
    const float* lavb    = (const float*)d_in[17];
    const float* lfvg    = (const float*)d_in[18];
    const float* lfvb    = (const float*)d_in[19];
    const float* lacg    = (const float*)d_in[20];
    const float* lacb    = (const float*)d_in[21];
    const float* lfcg    = (const float*)d_in[22];
    const float* lfcb    = (const float*)d_in[23];

    int E = in_sizes[2] / 2;

    float* buf;
    cudaGetSymbolAddress((void**)&buf, g_scratch);

    float* att  = buf + OFF_ATT;
    float* v1m  = buf + OFF_V1M;
    float* b768 = buf + OFF_B768;

    int* iarr  = (int*)(buf + OFF_IDX);
    int* deg   = iarr + IDX_DEG;
    int* excl  = iarr + IDX_EXCL;
    int* curp  = iarr + IDX_CUR;
    int* bsum  = iarr + IDX_BSUM;
    int* slots = iarr + IDX_SLOTS;

    __nv_bfloat16* bfb   = (__nv_bfloat16*)(buf + OFF_BF);
    __nv_bfloat16* xb    = bfb + B_XB;
    __nv_bfloat16* pb    = bfb + B_PB;
    __nv_bfloat16* x1b   = bfb + B_X1B;
    __nv_bfloat16* hidb  = bfb + B_HID;
    __nv_bfloat16* tmpb  = bfb + B_TMPB;
    __nv_bfloat16* wqkvb = bfb + B_WQKV;
    __nv_bfloat16* ffnw  = bfb + B_FFNW;
    __nv_bfloat16* fvw1b = ffnw;
    __nv_bfloat16* fvw2b = ffnw + 65536;
    __nv_bfloat16* fcw1b = ffnw + 131072;
    __nv_bfloat16* fcw2b = ffnw + 196608;

    __nv_bfloat16* pvb = pb;
    __nv_bfloat16* pcb = pb + (size_t)NVAR * 768;

    float* out_v = (float*)d_out;
    float* out_c = out_v + (size_t)NVAR * DIM;

    // ---- setup + CSR build ----
    cvt_x<<<(NTOT * 64 + 255) / 256, 256>>>(v, c, xb);
    setup_misc<<<1027, 256>>>(Wq, Wkv, bq, bkv, fvw1, fvw2, fcw1, fcw2,
                              wqkvb, ffnw, b768);
    cudaMemsetAsync(deg, 0, NSEG * sizeof(int), 0);
    count_deg<<<(2 * E + 255) / 256, 256>>>(adj_pos, adj_neg, E, deg);
    int nblk = (NSEG + 1023) / 1024;
    scan_blk<<<nblk, 1024>>>(deg, excl, bsum, NSEG);
    scan_top<<<1, 256>>>(bsum, nblk);
    add_off<<<nblk, 1024>>>(excl, curp, bsum, NSEG);
    fill_slots<<<(2 * E + 255) / 256, 256>>>(adj_pos, adj_neg, E, curp, slots);

    // ---- merged projection: 90000 x 768, packed bf16 [q|k|v] ----
    {
        dim3 grid(768 / BN, (NTOT + BM - 1) / BM);
        tgemm<<<grid, 256>>>(xb, 256, wqkvb, nullptr, 0, b768, b768,
                             nullptr, 0, 0, pb, 768, 768, NTOT, 768, 0);
    }

    // ---- gather attention ----
    gather_attn<<<(NVAR + 7) / 8, 256>>>(pvb, pcb, excl, curp, slots,
                                         0, NVAR, att, NVAR);
    gather_attn<<<(NCLS + 7) / 8, 256>>>(pcb, pvb, excl, curp, slots,
                                         2 * NVAR, 2 * NVAR + NCLS,
                                         att + (size_t)NVAR * 256, NCLS);

    // ---- merged attention LN ----
    ln_att_m<<<(NTOT + 7) / 8, 256>>>(v, c, att, lavg, lavb, lacg, lacb, v1m, x1b);

    // ---- merged FFN; FFN2 out bf16 ----
    {
        dim3 grid(256 / BN, (NTOTP + BM - 1) / BM);
        tgemm<<<grid, 256>>>(x1b, 256, fvw1b, fcw1b, NVP, fvb1, fcb1,
                             nullptr, 1 << 30, 0, hidb, 256, 256, NTOTP, 256, 1);
        tgemm<<<grid, 256>>>(hidb, 256, fvw2b, fcw2b, NVP, fvb2, fcb2,
                             nullptr, 1 << 30, 0, tmpb, 256, 256, NTOTP, 256, 0);
    }

    // ---- merged final LN ----
    ln_add_m<<<(NTOT + 7) / 8, 256>>>(v1m, tmpb, lfvg, lfvb, lfcg, lfcb, out_v, out_c);
}

// round 17
// speedup vs baseline: 1.4148x; 1.0324x over previous
#include <cuda_runtime.h>
#include <cuda_bf16.h>
#include <math.h>
#include <stdint.h>

#define NVAR 30000
#define NCLS 60000
#define NTOT 90000
#define NVP  30080
#define NTOTP 90080
#define DIM 256
#define NHEAD 8
#define NSEG (2 * NVAR + 2 * NCLS)

// ---------------- scratch layout (float units) ----------------
#define OFF_V1M    0ull             // 90080*256 fp32
#define OFF_B768   23060480ull      // 1024
#define OFF_IDX    23061504ull      // int area
#define IDX_DEG    0
#define IDX_EXCL   180000
#define IDX_CUR    360000
#define IDX_BSUM   540000
#define IDX_SLOTS  540256           // 480000
#define OFF_BF     24081760ull      // bf16 area (bf16-element offsets)
#define B_XB    0ull                // 90000*256
#define B_PB    23040000ull         // 90000*768 packed [q|k|v]
#define B_X1B   92160000ull         // 90080*256
#define B_HID   115220480ull
#define B_TMPB  138280960ull
#define B_WQKV  161341440ull        // 256*768
#define B_FFNW  161538048ull        // 4*65536
#define SCRATCH_TOTAL 104981856ull

__device__ float g_scratch[SCRATCH_TOTAL];

// ---------------- helpers ----------------
__device__ __forceinline__ void ldsm_x4(uint32_t* r, uint32_t saddr) {
    asm volatile("ldmatrix.sync.aligned.m8n8.x4.shared.b16 {%0,%1,%2,%3}, [%4];"
                 : "=r"(r[0]), "=r"(r[1]), "=r"(r[2]), "=r"(r[3]) : "r"(saddr));
}
__device__ __forceinline__ void ldsm_x4_trans(uint32_t* r, uint32_t saddr) {
    asm volatile("ldmatrix.sync.aligned.m8n8.x4.trans.shared.b16 {%0,%1,%2,%3}, [%4];"
                 : "=r"(r[0]), "=r"(r[1]), "=r"(r[2]), "=r"(r[3]) : "r"(saddr));
}
__device__ __forceinline__ void mma_bf16(float* d, const uint32_t* a, const uint32_t* b) {
    asm volatile(
        "mma.sync.aligned.m16n8k16.row.col.f32.bf16.bf16.f32 "
        "{%0,%1,%2,%3}, {%4,%5,%6,%7}, {%8,%9}, {%0,%1,%2,%3};"
        : "+f"(d[0]), "+f"(d[1]), "+f"(d[2]), "+f"(d[3])
        : "r"(a[0]), "r"(a[1]), "r"(a[2]), "r"(a[3]),
          "r"(b[0]), "r"(b[1]));
}
__device__ __forceinline__ void cp_async16(uint32_t saddr, const void* gaddr, int src_size) {
    asm volatile("cp.async.cg.shared.global [%0], [%1], 16, %2;"
                 :: "r"(saddr), "l"(gaddr), "r"(src_size));
}
#define CP_COMMIT() asm volatile("cp.async.commit_group;" ::: "memory")
#define CP_WAIT0()  asm volatile("cp.async.wait_group 0;" ::: "memory")

// ---------------- merged setup: cvt inputs + weights + bias ----------------
// blocks [0,22500): cvt x; [22500,22756): FFN weights; [22756,23524): wqkv; [23524,23527): bias
#define SETUP_BLOCKS 23527
__global__ void setup_all(const float* __restrict__ v, const float* __restrict__ c,
                          __nv_bfloat16* __restrict__ xb,
                          const float* __restrict__ Wq, const float* __restrict__ Wkv,
                          const float* __restrict__ bq, const float* __restrict__ bkv,
                          const float* __restrict__ w1, const float* __restrict__ w2,
                          const float* __restrict__ w3, const float* __restrict__ w4,
                          __nv_bfloat16* __restrict__ wqkvb,
                          __nv_bfloat16* __restrict__ ffnw,
                          float* __restrict__ b768) {
    int blk = blockIdx.x;
    int tid = threadIdx.x;
    if (blk < 22500) {
        int i = blk * 256 + tid;
        const float* src = (i < NVAR * 64) ? v : c - (size_t)NVAR * 256;
        float4 t = ((const float4*)src)[i];
        __nv_bfloat162 lo = __float22bfloat162_rn(make_float2(t.x, t.y));
        __nv_bfloat162 hi = __float22bfloat162_rn(make_float2(t.z, t.w));
        ((uint2*)xb)[i] = make_uint2(*(uint32_t*)&lo, *(uint32_t*)&hi);
    } else if (blk < 22756) {
        int i = (blk - 22500) * 256 + tid;
        int which = i >> 14;
        int j = i & 16383;
        const float* src = (which == 0) ? w1 : (which == 1) ? w2 : (which == 2) ? w3 : w4;
        float4 t = ((const float4*)src)[j];
        __nv_bfloat162 lo = __float22bfloat162_rn(make_float2(t.x, t.y));
        __nv_bfloat162 hi = __float22bfloat162_rn(make_float2(t.z, t.w));
        ((uint2*)(ffnw + (size_t)which * 65536))[j] =
            make_uint2(*(uint32_t*)&lo, *(uint32_t*)&hi);
    } else if (blk < 23524) {
        int i = (blk - 22756) * 256 + tid;
        int k = i / 768, j = i % 768;
        float val = (j < 256) ? Wq[k * 256 + j] : Wkv[k * 512 + (j - 256)];
        wqkvb[i] = __float2bfloat16(val);
    } else {
        int j = (blk - 23524) * 256 + tid;
        if (j < 768) b768[j] = (j < 256) ? bq[j] : bkv[j - 256];
    }
}

// ---------------- CSR build ----------------
__global__ void count_deg(const int* __restrict__ adj_pos, const int* __restrict__ adj_neg,
                          int E, int* __restrict__ deg) {
    int i = blockIdx.x * blockDim.x + threadIdx.x;
    if (i >= 2 * E) return;
    int pol = i >= E;
    int e = i - (pol ? E : 0);
    const int* adj = pol ? adj_neg : adj_pos;
    int cn = adj[e], vn = adj[E + e];
    atomicAdd(&deg[(pol ? NVAR : 0) + vn], 1);
    atomicAdd(&deg[2 * NVAR + (pol ? NCLS : 0) + cn], 1);
}

__global__ void scan_blk(const int* __restrict__ deg, int* __restrict__ excl,
                         int* __restrict__ bsum, int n) {
    __shared__ int ws[32];
    int idx = blockIdx.x * 1024 + threadIdx.x;
    int lane = threadIdx.x & 31;
    int warp = threadIdx.x >> 5;
    int orig = (idx < n) ? deg[idx] : 0;
    int val = orig;
    #pragma unroll
    for (int off = 1; off < 32; off <<= 1) {
        int t = __shfl_up_sync(0xffffffffu, val, off);
        if (lane >= off) val += t;
    }
    if (lane == 31) ws[warp] = val;
    __syncthreads();
    if (warp == 0) {
        int w = ws[lane];
        #pragma unroll
        for (int off = 1; off < 32; off <<= 1) {
            int t = __shfl_up_sync(0xffffffffu, w, off);
            if (lane >= off) w += t;
        }
        ws[lane] = w;
    }
    __syncthreads();
    int incl = val + (warp > 0 ? ws[warp - 1] : 0);
    if (idx < n) excl[idx] = incl - orig;
    if (threadIdx.x == 1023) bsum[blockIdx.x] = incl;
}

__global__ void scan_top(int* __restrict__ bsum, int nb) {
    __shared__ int sh[256];
    int tid = threadIdx.x;
    sh[tid] = (tid < nb) ? bsum[tid] : 0;
    __syncthreads();
    if (tid == 0) {
        int run = 0;
        for (int i = 0; i < nb; i++) { int t = sh[i]; sh[i] = run; run += t; }
    }
    __syncthreads();
    if (tid < nb) bsum[tid] = sh[tid];
}

__global__ void add_off(int* __restrict__ excl, int* __restrict__ cur,
                        const int* __restrict__ bsum, int n) {
    int idx = blockIdx.x * 1024 + threadIdx.x;
    if (idx >= n) return;
    int v = excl[idx] + bsum[blockIdx.x];
    excl[idx] = v;
    cur[idx] = v;
}

__global__ void fill_slots(const int* __restrict__ adj_pos, const int* __restrict__ adj_neg,
                           int E, int* __restrict__ cur, int* __restrict__ slots) {
    int i = blockIdx.x * blockDim.x + threadIdx.x;
    if (i >= 2 * E) return;
    int pol = i >= E;
    int e = i - (pol ? E : 0);
    const int* adj = pol ? adj_neg : adj_pos;
    int cn = adj[e], vn = adj[E + e];
    int s1 = atomicAdd(&cur[(pol ? NVAR : 0) + vn], 1);
    slots[s1] = cn;
    int s2 = atomicAdd(&cur[2 * NVAR + (pol ? NCLS : 0) + cn], 1);
    slots[s2] = vn;
}

// ---------------- fused gather attention + LN: one warp per node ----------------
// Packed rows stride 768: q +0, k +256, v +512. lane owns dims [lane*8, lane*8+8).
__global__ void gather_ln(
    const __nv_bfloat16* __restrict__ pb,
    const int* __restrict__ excl, const int* __restrict__ cur,
    const int* __restrict__ slots,
    const float* __restrict__ xv, const float* __restrict__ xc,
    const float* __restrict__ gv, const float* __restrict__ bv,
    const float* __restrict__ gc, const float* __restrict__ bc,
    float* __restrict__ y, __nv_bfloat16* __restrict__ yb)
{
    int gw = blockIdx.x * (blockDim.x >> 5) + (threadIdx.x >> 5);
    int lane = threadIdx.x & 31;
    if (gw >= NTOT) return;
    bool isv = gw < NVAR;
    int node = isv ? gw : gw - NVAR;
    const __nv_bfloat16* Qb  = isv ? pb : pb + (size_t)NVAR * 768;
    const __nv_bfloat16* KVb = isv ? pb + (size_t)NVAR * 768 : pb;
    int li0 = (isv ? 0 : 2 * NVAR) + node;
    int li1 = (isv ? NVAR : 2 * NVAR + NCLS) + node;

    float qf[8];
    {
        uint4 qu = *(const uint4*)&Qb[(size_t)node * 768 + lane * 8];
        const __nv_bfloat162* qp = (const __nv_bfloat162*)&qu;
        #pragma unroll
        for (int i = 0; i < 4; i++) {
            float2 f = __bfloat1622float2(qp[i]);
            qf[i * 2] = f.x; qf[i * 2 + 1] = f.y;
        }
    }

    float res[8];
    #pragma unroll
    for (int i = 0; i < 8; i++) res[i] = 0.0f;

    #pragma unroll
    for (int L = 0; L < 2; L++) {
        int li = L ? li1 : li0;
        int j0 = excl[li], j1 = cur[li];
        float den = 0.0f;
        float acc[8];
        #pragma unroll
        for (int i = 0; i < 8; i++) acc[i] = 0.0f;
        for (int j = j0; j < j1; j++) {
            int src = slots[j];
            const __nv_bfloat16* row = &KVb[(size_t)src * 768];
            uint4 ku = *(const uint4*)&row[256 + lane * 8];
            const __nv_bfloat162* kp = (const __nv_bfloat162*)&ku;
            float p = 0.0f;
            #pragma unroll
            for (int i = 0; i < 4; i++) {
                float2 f = __bfloat1622float2(kp[i]);
                p += qf[i * 2] * f.x + qf[i * 2 + 1] * f.y;
            }
            p += __shfl_xor_sync(0xffffffffu, p, 1);
            p += __shfl_xor_sync(0xffffffffu, p, 2);
            float e = __expf(p * 0.17677669529663687f);
            den += e;
            uint4 vu = *(const uint4*)&row[512 + lane * 8];
            const __nv_bfloat162* vp = (const __nv_bfloat162*)&vu;
            #pragma unroll
            for (int i = 0; i < 4; i++) {
                float2 f = __bfloat1622float2(vp[i]);
                acc[i * 2]     += e * f.x;
                acc[i * 2 + 1] += e * f.y;
            }
        }
        if (den > 0.0f) {
            #pragma unroll
            for (int i = 0; i < 8; i++) res[i] += acc[i] / den;
        }
    }

    // ---- fused LN(x + res) ----
    const float* x = isv ? xv : xc;
    float vals[8];
    {
        float4 x0 = *(const float4*)&x[(size_t)node * 256 + lane * 8];
        float4 x1 = *(const float4*)&x[(size_t)node * 256 + lane * 8 + 4];
        vals[0] = x0.x + res[0]; vals[1] = x0.y + res[1];
        vals[2] = x0.z + res[2]; vals[3] = x0.w + res[3];
        vals[4] = x1.x + res[4]; vals[5] = x1.y + res[5];
        vals[6] = x1.z + res[6]; vals[7] = x1.w + res[7];
    }
    float s = 0.0f;
    #pragma unroll
    for (int i = 0; i < 8; i++) s += vals[i];
    #pragma unroll
    for (int o = 16; o > 0; o >>= 1) s += __shfl_xor_sync(0xffffffffu, s, o);
    float mean = s * (1.0f / 256.0f);
    float v2 = 0.0f;
    #pragma unroll
    for (int i = 0; i < 8; i++) { float d = vals[i] - mean; v2 += d * d; }
    #pragma unroll
    for (int o = 16; o > 0; o >>= 1) v2 += __shfl_xor_sync(0xffffffffu, v2, o);
    float rstd = rsqrtf(v2 * (1.0f / 256.0f) + 1e-5f);

    const float* g = isv ? gv : gc;
    const float* b = isv ? bv : bc;
    float4 g0 = *(const float4*)&g[lane * 8];
    float4 g1 = *(const float4*)&g[lane * 8 + 4];
    float4 b0 = *(const float4*)&b[lane * 8];
    float4 b1 = *(const float4*)&b[lane * 8 + 4];

    float o0 = (vals[0] - mean) * rstd * g0.x + b0.x;
    float o1 = (vals[1] - mean) * rstd * g0.y + b0.y;
    float o2 = (vals[2] - mean) * rstd * g0.z + b0.z;
    float o3 = (vals[3] - mean) * rstd * g0.w + b0.w;
    float o4 = (vals[4] - mean) * rstd * g1.x + b1.x;
    float o5 = (vals[5] - mean) * rstd * g1.y + b1.y;
    float o6 = (vals[6] - mean) * rstd * g1.z + b1.z;
    float o7 = (vals[7] - mean) * rstd * g1.w + b1.w;

    size_t orow = isv ? (size_t)gw : (size_t)NVP + node;
    *(float4*)&y[orow * 256 + lane * 8]     = make_float4(o0, o1, o2, o3);
    *(float4*)&y[orow * 256 + lane * 8 + 4] = make_float4(o4, o5, o6, o7);

    __nv_bfloat162 p0 = __float22bfloat162_rn(make_float2(o0, o1));
    __nv_bfloat162 p1 = __float22bfloat162_rn(make_float2(o2, o3));
    __nv_bfloat162 p2 = __float22bfloat162_rn(make_float2(o4, o5));
    __nv_bfloat162 p3 = __float22bfloat162_rn(make_float2(o6, o7));
    *(uint4*)&yb[orow * 256 + lane * 8] =
        make_uint4(*(uint32_t*)&p0, *(uint32_t*)&p1, *(uint32_t*)&p2, *(uint32_t*)&p3);
}

// ---------------- bf16 tensor-core GEMM ----------------
#define BM 128
#define BN 128
#define BK 32
#define ASTR 40
#define BSTR 136

__global__ __launch_bounds__(256, 2) void tgemm(
    const __nv_bfloat16* __restrict__ A, int lda,
    const __nv_bfloat16* __restrict__ W1, const __nv_bfloat16* __restrict__ W2, int nsplit,
    const float* __restrict__ bias1, const float* __restrict__ bias2,
    float* __restrict__ C, int cfrom, int cs,
    __nv_bfloat16* __restrict__ Cb, int cbto, int cbs,
    int N, int M, int gelu)
{
    __shared__ __nv_bfloat16 As[2][BM * ASTR];
    __shared__ __nv_bfloat16 Ws[2][BK * BSTR];

    int tid = threadIdx.x;
    int lane = tid & 31;
    int warp = tid >> 5;
    int wm = (warp & 3) * 32;
    int wn = (warp >> 2) * 64;
    int bm = blockIdx.y * BM;
    int bn = blockIdx.x * BN;

    bool second = (W2 != nullptr) && (bm >= nsplit);
    const __nv_bfloat16* W = second ? W2 : W1;
    const float* bias = second ? bias2 : bias1;

    uint32_t as_base = (uint32_t)__cvta_generic_to_shared(&As[0][0]);
    uint32_t ws_base = (uint32_t)__cvta_generic_to_shared(&Ws[0][0]);
    const uint32_t as_sz = BM * ASTR * 2;
    const uint32_t ws_sz = BK * BSTR * 2;

    int a_row[2], a_col[2], w_row[2], w_col[2];
    uint32_t a_dst[2], w_dst[2];
    #pragma unroll
    for (int i = 0; i < 2; i++) {
        int g = tid + i * 256;
        a_row[i] = (tid * 2 + i) >> 2;
        a_col[i] = ((tid * 2 + i) & 3) * 8;
        w_row[i] = g >> 4;
        w_col[i] = (g & 15) * 8;
        a_dst[i] = as_base + (uint32_t)(a_row[i] * ASTR + a_col[i]) * 2;
        w_dst[i] = ws_base + (uint32_t)(w_row[i] * BSTR + w_col[i]) * 2;
    }

    float acc[2][8][4];
    #pragma unroll
    for (int mt = 0; mt < 2; mt++)
        #pragma unroll
        for (int nt = 0; nt < 8; nt++)
            #pragma unroll
            for (int i = 0; i < 4; i++) acc[mt][nt][i] = 0.0f;

    int a_r = lane & 15;
    int a_c = (lane >> 4) * 8;

    #pragma unroll
    for (int i = 0; i < 2; i++) {
        int gr = bm + a_row[i];
        cp_async16(a_dst[i], &A[(size_t)gr * lda + a_col[i]], (gr < N) ? 16 : 0);
        cp_async16(w_dst[i], &W[(size_t)w_row[i] * M + bn + w_col[i]], 16);
    }
    CP_COMMIT();
    CP_WAIT0();
    __syncthreads();

    for (int s = 0; s < 8; s++) {
        int cur_ = s & 1, nxt = cur_ ^ 1;
        if (s < 7) {
            int k0 = (s + 1) * BK;
            #pragma unroll
            for (int i = 0; i < 2; i++) {
                int gr = bm + a_row[i];
                cp_async16(a_dst[i] + nxt * as_sz,
                           &A[(size_t)gr * lda + k0 + a_col[i]], (gr < N) ? 16 : 0);
                cp_async16(w_dst[i] + nxt * ws_sz,
                           &W[(size_t)(k0 + w_row[i]) * M + bn + w_col[i]], 16);
            }
            CP_COMMIT();
        }

        uint32_t asb = as_base + cur_ * as_sz;
        uint32_t wsb = ws_base + cur_ * ws_sz;
        #pragma unroll
        for (int ks = 0; ks < 2; ks++) {
            int kb = ks * 16;
            uint32_t af[2][4], bf[4][4];
            #pragma unroll
            for (int mt = 0; mt < 2; mt++) {
                int row = wm + mt * 16 + a_r;
                int col = kb + a_c;
                ldsm_x4(af[mt], asb + (uint32_t)(row * ASTR + col) * 2);
            }
            #pragma unroll
            for (int p = 0; p < 4; p++) {
                int row = kb + (lane & 15);
                int col = wn + p * 16 + (lane >> 4) * 8;
                ldsm_x4_trans(bf[p], wsb + (uint32_t)(row * BSTR + col) * 2);
            }
            #pragma unroll
            for (int mt = 0; mt < 2; mt++)
                #pragma unroll
                for (int nt = 0; nt < 8; nt++)
                    mma_bf16(acc[mt][nt], af[mt], &bf[nt >> 1][(nt & 1) * 2]);
        }

        if (s < 7) {
            CP_WAIT0();
            __syncthreads();
        }
    }

    #pragma unroll
    for (int mt = 0; mt < 2; mt++) {
        int r0 = bm + wm + mt * 16 + (lane >> 2);
        #pragma unroll
        for (int nt = 0; nt < 8; nt++) {
            int cb = bn + wn + nt * 8 + (lane & 3) * 2;
            float b0 = bias[cb], b1 = bias[cb + 1];
            float2 lo = make_float2(acc[mt][nt][0] + b0, acc[mt][nt][1] + b1);
            float2 hi = make_float2(acc[mt][nt][2] + b0, acc[mt][nt][3] + b1);
            if (gelu) {
                lo.x = 0.5f * lo.x * (1.0f + erff(lo.x * 0.70710678118654752f));
                lo.y = 0.5f * lo.y * (1.0f + erff(lo.y * 0.70710678118654752f));
                hi.x = 0.5f * hi.x * (1.0f + erff(hi.x * 0.70710678118654752f));
                hi.y = 0.5f * hi.y * (1.0f + erff(hi.y * 0.70710678118654752f));
            }
            if (C && cb >= cfrom) {
                if (r0 < N)     *(float2*)&C[(size_t)r0 * cs + cb - cfrom] = lo;
                if (r0 + 8 < N) *(float2*)&C[(size_t)(r0 + 8) * cs + cb - cfrom] = hi;
            }
            if (Cb && cb < cbto) {
                __nv_bfloat162 blo = __float22bfloat162_rn(lo);
                __nv_bfloat162 bhi = __float22bfloat162_rn(hi);
                if (r0 < N)     *(__nv_bfloat162*)&Cb[(size_t)r0 * cbs + cb] = blo;
                if (r0 + 8 < N) *(__nv_bfloat162*)&Cb[(size_t)(r0 + 8) * cbs + cb] = bhi;
            }
        }
    }
}

// ---------------- merged final LN: y = LN(x + a_bf16) ----------------
__global__ void ln_add_m(const float* __restrict__ x, const __nv_bfloat16* __restrict__ a,
                         const float* __restrict__ gv, const float* __restrict__ bv,
                         const float* __restrict__ gc, const float* __restrict__ bc,
                         float* __restrict__ out_v, float* __restrict__ out_c)
{
    int gr = blockIdx.x * (blockDim.x >> 5) + (threadIdx.x >> 5);
    int lane = threadIdx.x & 31;
    if (gr >= NTOT) return;
    bool isv = gr < NVAR;
    int node = isv ? gr : gr - NVAR;
    size_t brow = isv ? (size_t)gr : (size_t)NVP + node;
    const float* g = isv ? gv : gc;
    const float* b = isv ? bv : bc;
    float* y = isv ? out_v : out_c;

    float vals[8];
    float s = 0.0f;
    #pragma unroll
    for (int i = 0; i < 8; i++) {
        size_t idx = brow * 256 + i * 32 + lane;
        vals[i] = x[idx] + __bfloat162float(a[idx]);
        s += vals[i];
    }
    #pragma unroll
    for (int o = 16; o > 0; o >>= 1) s += __shfl_xor_sync(0xffffffffu, s, o);
    float mean = s * (1.0f / 256.0f);
    float v2 = 0.0f;
    #pragma unroll
    for (int i = 0; i < 8; i++) { float d = vals[i] - mean; v2 += d * d; }
    #pragma unroll
    for (int o = 16; o > 0; o >>= 1) v2 += __shfl_xor_sync(0xffffffffu, v2, o);
    float rstd = rsqrtf(v2 * (1.0f / 256.0f) + 1e-5f);
    #pragma unroll
    for (int i = 0; i < 8; i++) {
        int cidx = i * 32 + lane;
        y[(size_t)node * 256 + cidx] = (vals[i] - mean) * rstd * g[cidx] + b[cidx];
    }
}

extern "C" void kernel_launch(void* const* d_in, const int* in_sizes, int n_in,
                              void* d_out, int out_size)
{
    const float* v       = (const float*)d_in[0];
    const float* c       = (const float*)d_in[1];
    const int*   adj_pos = (const int*)d_in[2];
    const int*   adj_neg = (const int*)d_in[3];
    const float* Wq      = (const float*)d_in[4];
    const float* bq      = (const float*)d_in[5];
    const float* Wkv     = (const float*)d_in[6];
    const float* bkv     = (const float*)d_in[7];
    const float* fvw1    = (const float*)d_in[8];
    const float* fvb1    = (const float*)d_in[9];
    const float* fvw2    = (const float*)d_in[10];
    const float* fvb2    = (const float*)d_in[11];
    const float* fcw1    = (const float*)d_in[12];
    const float* fcb1    = (const float*)d_in[13];
    const float* fcw2    = (const float*)d_in[14];
    const float* fcb2    = (const float*)d_in[15];
    const float* lavg    = (const float*)d_in[16];
    const float* lavb    = (const float*)d_in[17];
    const float* lfvg    = (const float*)d_in[18];
    const float* lfvb    = (const float*)d_in[19];
    const float* lacg    = (const float*)d_in[20];
    const float* lacb    = (const float*)d_in[21];
    const float* lfcg    = (const float*)d_in[22];
    const float* lfcb    = (const float*)d_in[23];

    int E = in_sizes[2] / 2;

    float* buf;
    cudaGetSymbolAddress((void**)&buf, g_scratch);

    float* v1m  = buf + OFF_V1M;
    float* b768 = buf + OFF_B768;

    int* iarr  = (int*)(buf + OFF_IDX);
    int* deg   = iarr + IDX_DEG;
    int* excl  = iarr + IDX_EXCL;
    int* curp  = iarr + IDX_CUR;
    int* bsum  = iarr + IDX_BSUM;
    int* slots = iarr + IDX_SLOTS;

    __nv_bfloat16* bfb   = (__nv_bfloat16*)(buf + OFF_BF);
    __nv_bfloat16* xb    = bfb + B_XB;
    __nv_bfloat16* pb    = bfb + B_PB;
    __nv_bfloat16* x1b   = bfb + B_X1B;
    __nv_bfloat16* hidb  = bfb + B_HID;
    __nv_bfloat16* tmpb  = bfb + B_TMPB;
    __nv_bfloat16* wqkvb = bfb + B_WQKV;
    __nv_bfloat16* ffnw  = bfb + B_FFNW;
    __nv_bfloat16* fvw1b = ffnw;
    __nv_bfloat16* fvw2b = ffnw + 65536;
    __nv_bfloat16* fcw1b = ffnw + 131072;
    __nv_bfloat16* fcw2b = ffnw + 196608;

    float* out_v = (float*)d_out;
    float* out_c = out_v + (size_t)NVAR * DIM;

    // ---- setup + CSR build ----
    setup_all<<<SETUP_BLOCKS, 256>>>(v, c, xb, Wq, Wkv, bq, bkv,
                                     fvw1, fvw2, fcw1, fcw2, wqkvb, ffnw, b768);
    cudaMemsetAsync(deg, 0, NSEG * sizeof(int), 0);
    count_deg<<<(2 * E + 255) / 256, 256>>>(adj_pos, adj_neg, E, deg);
    int nblk = (NSEG + 1023) / 1024;
    scan_blk<<<nblk, 1024>>>(deg, excl, bsum, NSEG);
    scan_top<<<1, 256>>>(bsum, nblk);
    add_off<<<nblk, 1024>>>(excl, curp, bsum, NSEG);
    fill_slots<<<(2 * E + 255) / 256, 256>>>(adj_pos, adj_neg, E, curp, slots);

    // ---- merged projection: 90000 x 768, packed bf16 [q|k|v] ----
    {
        dim3 grid(768 / BN, (NTOT + BM - 1) / BM);
        tgemm<<<grid, 256>>>(xb, 256, wqkvb, nullptr, 0, b768, b768,
                             nullptr, 0, 0, pb, 768, 768, NTOT, 768, 0);
    }

    // ---- fused gather attention + LN (single launch, all nodes) ----
    gather_ln<<<(NTOT + 7) / 8, 256>>>(pb, excl, curp, slots, v, c,
                                       lavg, lavb, lacg, lacb, v1m, x1b);

    // ---- merged FFN; FFN2 out bf16 ----
    {
        dim3 grid(256 / BN, (NTOTP + BM - 1) / BM);
        tgemm<<<grid, 256>>>(x1b, 256, fvw1b, fcw1b, NVP, fvb1, fcb1,
                             nullptr, 1 << 30, 0, hidb, 256, 256, NTOTP, 256, 1);
        tgemm<<<grid, 256>>>(hidb, 256, fvw2b, fcw2b, NVP, fvb2, fcb2,
                             nullptr, 1 << 30, 0, tmpb, 256, 256, NTOTP, 256, 0);
    }

    // ---- merged final LN ----
    ln_add_m<<<(NTOT + 7) / 8, 256>>>(v1m, tmpb, lfvg, lfvb, lfcg, lfcb, out_v, out_c);
}